// round 1
// baseline (speedup 1.0000x reference)
#include <cuda_runtime.h>
#include <math.h>
#include <stdint.h>

#define NT 8192
#define NS 8192
#define FD 128
#define KSEL 2457
#define BN_EPS 1e-5f
#define KEYSPACE (2*64*128*128)   /* 2097152 */
#define INV_TAU (1.0f/0.07f)
#define NBINS 4096
#define CAND_MAX 2048

// ---------------- scratch (device globals; no allocation in kernel_launch) ------------
__device__ __align__(16) float g_tmpA[NS*FD];
__device__ __align__(16) float g_h2[2][NS*FD];
__device__ __align__(16) float g_proj[2][NS*FD];
__device__ __align__(16) float g_sims[(size_t)NS*NT];   // 256MB
__device__ int   g_keymap[KEYSPACE];
__device__ int   g_matched[NS];
__device__ int   g_tidx[NS];
__device__ int   g_cnt;
__device__ float g_accum;
__device__ float g_bn_sum[2][FD];
__device__ float g_bn_sq[2][FD];
__device__ float g_bn_scale[2][FD];
__device__ float g_bn_shift[2][FD];

// fast exp via exp(t) Taylor on |t|<=0.347 after range reduction (FFMA pipe, no MUFU)
__device__ __forceinline__ float fexp(float x) {
    float y = x * 1.44269504088896340736f;
    float n = rintf(y);
    float t = (y - n) * 0.69314718055994530942f;
    float p = 1.0f/720.0f;
    p = fmaf(p, t, 1.0f/120.0f);
    p = fmaf(p, t, 1.0f/24.0f);
    p = fmaf(p, t, 1.0f/6.0f);
    p = fmaf(p, t, 0.5f);
    p = fmaf(p, t, 1.0f);
    p = fmaf(p, t, 1.0f);
    int ni = (int)n;
    return p * __int_as_float((ni + 127) << 23);
}

__device__ __forceinline__ unsigned okey(float f) {
    unsigned b = __float_as_uint(f);
    return (b & 0x80000000u) ? ~b : (b | 0x80000000u);
}
__device__ __forceinline__ float kval(unsigned u) {
    unsigned b = (u & 0x80000000u) ? (u & 0x7FFFFFFFu) : ~u;
    return __uint_as_float(b);
}

// ---------------- init: reset all mutable state every launch --------------------------
__global__ void k_init() {
    int idx = blockIdx.x * 256 + threadIdx.x;
    if (idx < KEYSPACE) g_keymap[idx] = -1;
    if (idx < NS) g_matched[idx] = 0;
    if (idx < 2*FD) {
        ((float*)g_bn_sum)[idx] = 0.f;
        ((float*)g_bn_sq)[idx]  = 0.f;
    }
    if (idx == 0) { g_cnt = 0; g_accum = 0.f; }
}

// ---------------- projection GEMM: out[r][c] = act(sum_k x[r][k] w[k][c] + b[c]) ------
// 128 threads, 16 rows per CTA. W(64KB) + X tile(8KB) + bias in dynamic smem.
__global__ void k_proj_gemm(const float* __restrict__ xext, int xsel,
                            const float* __restrict__ w, const float* __restrict__ bias,
                            int dst, int relu) {
    extern __shared__ float sm[];
    float* Ws = sm;              // 128*128
    float* Xs = sm + 16384;      // 16*128
    float* Bs = sm + 16384 + 2048;
    const float* x = xsel ? g_tmpA : xext;
    float* out = (dst == 0) ? g_tmpA : g_h2[dst - 1];
    int tid = threadIdx.x;
    const float4* w4 = (const float4*)w;
    #pragma unroll
    for (int i = 0; i < 32; i++) ((float4*)Ws)[tid + i*128] = w4[tid + i*128];
    int r0 = blockIdx.x * 16;
    const float4* x4 = (const float4*)(x + (size_t)r0 * FD);
    #pragma unroll
    for (int i = 0; i < 4; i++) ((float4*)Xs)[tid + i*128] = x4[tid + i*128];
    Bs[tid] = bias[tid & 127];
    __syncthreads();
    int cg = tid & 31, rq = tid >> 5;
    float4 acc[4];
    #pragma unroll
    for (int i = 0; i < 4; i++) acc[i] = make_float4(0.f,0.f,0.f,0.f);
    for (int k = 0; k < 128; k++) {
        float4 wv = *(float4*)&Ws[k*128 + cg*4];
        #pragma unroll
        for (int rr = 0; rr < 4; rr++) {
            float xv = Xs[(rq*4+rr)*128 + k];
            acc[rr].x = fmaf(xv, wv.x, acc[rr].x);
            acc[rr].y = fmaf(xv, wv.y, acc[rr].y);
            acc[rr].z = fmaf(xv, wv.z, acc[rr].z);
            acc[rr].w = fmaf(xv, wv.w, acc[rr].w);
        }
    }
    #pragma unroll
    for (int rr = 0; rr < 4; rr++) {
        float4 o;
        o.x = acc[rr].x + Bs[cg*4+0];
        o.y = acc[rr].y + Bs[cg*4+1];
        o.z = acc[rr].z + Bs[cg*4+2];
        o.w = acc[rr].w + Bs[cg*4+3];
        if (relu) {
            o.x = fmaxf(o.x, 0.f); o.y = fmaxf(o.y, 0.f);
            o.z = fmaxf(o.z, 0.f); o.w = fmaxf(o.w, 0.f);
        }
        *(float4*)&out[(size_t)(r0 + rq*4 + rr)*FD + cg*4] = o;
    }
}

// ---------------- BN stats: per-column sum / sumsq over 8192 rows ---------------------
__global__ void k_bnstat(int net) {
    const float* h = g_h2[net];
    int c = threadIdx.x;
    int r0 = blockIdx.x * 64;
    float s = 0.f, q = 0.f;
    for (int r = 0; r < 64; r++) {
        float v = h[(size_t)(r0 + r)*FD + c];
        s += v; q = fmaf(v, v, q);
    }
    atomicAdd(&g_bn_sum[net][c], s);
    atomicAdd(&g_bn_sq[net][c], q);
}

__global__ void k_bnfinal(const float* __restrict__ tg, const float* __restrict__ tb,
                          const float* __restrict__ sg, const float* __restrict__ sb) {
    int idx = threadIdx.x;
    int net = idx >> 7, c = idx & 127;
    const float* gam = net ? sg : tg;
    const float* bet = net ? sb : tb;
    float mu  = g_bn_sum[net][c] * (1.0f/8192.0f);
    float var = g_bn_sq[net][c]  * (1.0f/8192.0f) - mu*mu;
    float sc  = rsqrtf(var + BN_EPS) * gam[c];
    g_bn_scale[net][c] = sc;
    g_bn_shift[net][c] = bet[c] - mu * sc;
}

// ---------------- BN apply + L2 row-normalize: warp per row ---------------------------
__global__ void k_norm(int net) {
    const float* h = g_h2[net];
    float* p = g_proj[net];
    int w = threadIdx.x >> 5, l = threadIdx.x & 31;
    int r = blockIdx.x * 8 + w;
    float4 v  = *(const float4*)&h[(size_t)r*FD + l*4];
    float4 sc = *(const float4*)&g_bn_scale[net][l*4];
    float4 sh = *(const float4*)&g_bn_shift[net][l*4];
    float4 y;
    y.x = fmaf(v.x, sc.x, sh.x); y.y = fmaf(v.y, sc.y, sh.y);
    y.z = fmaf(v.z, sc.z, sh.z); y.w = fmaf(v.w, sc.w, sh.w);
    float ss = y.x*y.x + y.y*y.y + y.z*y.z + y.w*y.w;
    #pragma unroll
    for (int o = 16; o > 0; o >>= 1) ss += __shfl_xor_sync(0xffffffffu, ss, o);
    float inv = rsqrtf(ss);
    y.x *= inv; y.y *= inv; y.z *= inv; y.w *= inv;
    *(float4*)&p[(size_t)r*FD + l*4] = y;
}

// ---------------- coord matching via inverse map --------------------------------------
__global__ void k_scatter(const int* __restrict__ tc) {
    int i = blockIdx.x * 256 + threadIdx.x;
    if (i >= NT) return;
    int4 c = ((const int4*)tc)[i];
    int key = ((c.x * 64 + c.y) * 128 + c.z) * 128 + c.w;
    g_keymap[key] = i;
}
__global__ void k_match(const int* __restrict__ sc) {
    int j = blockIdx.x * 256 + threadIdx.x;
    if (j >= NS) return;
    int4 c = ((const int4*)sc)[j];
    int key = ((c.x * 64 + c.y) * 128 + c.z) * 128 + c.w;
    int t = g_keymap[key];
    g_tidx[j] = (t < 0) ? 0 : t;
    if (t >= 0) {
        int p = atomicAdd(&g_cnt, 1);
        g_matched[p] = j;
    }
}

// ---------------- sims GEMM (matched rows only): 128x128 tile, 8x8 per thread ---------
#define APAD 132
__global__ void k_gemm() {
    if ((int)(blockIdx.y * 128) >= g_cnt) return;
    extern __shared__ float sm[];
    float* As  = sm;                 // [128][132] k-major
    float* Bsm = sm + 128*APAD;      // [128][132] k-major
    const float* sp = g_proj[1];
    const float* tp = g_proj[0];
    int tid = threadIdx.x;
    #pragma unroll
    for (int it = 0; it < 16; it++) {
        int idx = tid + it*256;
        int m = idx >> 5, kq = idx & 31;
        int row = g_matched[blockIdx.y*128 + m];
        float4 v = *(const float4*)&sp[(size_t)row*FD + kq*4];
        As[(kq*4+0)*APAD + m] = v.x;
        As[(kq*4+1)*APAD + m] = v.y;
        As[(kq*4+2)*APAD + m] = v.z;
        As[(kq*4+3)*APAD + m] = v.w;
        int trow = blockIdx.x*128 + m;
        float4 u = *(const float4*)&tp[(size_t)trow*FD + kq*4];
        Bsm[(kq*4+0)*APAD + m] = u.x;
        Bsm[(kq*4+1)*APAD + m] = u.y;
        Bsm[(kq*4+2)*APAD + m] = u.z;
        Bsm[(kq*4+3)*APAD + m] = u.w;
    }
    __syncthreads();
    int tx = tid & 15, ty = tid >> 4;
    float acc[8][8];
    #pragma unroll
    for (int i = 0; i < 8; i++)
        #pragma unroll
        for (int j = 0; j < 8; j++) acc[i][j] = 0.f;
    for (int k = 0; k < 128; k++) {
        float4 a0 = *(float4*)&As[k*APAD + ty*8];
        float4 a1 = *(float4*)&As[k*APAD + ty*8 + 4];
        float4 b0 = *(float4*)&Bsm[k*APAD + tx*8];
        float4 b1 = *(float4*)&Bsm[k*APAD + tx*8 + 4];
        float a[8] = {a0.x,a0.y,a0.z,a0.w,a1.x,a1.y,a1.z,a1.w};
        float b[8] = {b0.x,b0.y,b0.z,b0.w,b1.x,b1.y,b1.z,b1.w};
        #pragma unroll
        for (int i = 0; i < 8; i++)
            #pragma unroll
            for (int j = 0; j < 8; j++)
                acc[i][j] = fmaf(a[i], b[j], acc[i][j]);
    }
    #pragma unroll
    for (int i = 0; i < 8; i++) {
        size_t base = (size_t)(blockIdx.y*128 + ty*8 + i) * NT + blockIdx.x*128 + tx*8;
        float4 o0, o1;
        o0.x = acc[i][0]*INV_TAU; o0.y = acc[i][1]*INV_TAU;
        o0.z = acc[i][2]*INV_TAU; o0.w = acc[i][3]*INV_TAU;
        o1.x = acc[i][4]*INV_TAU; o1.y = acc[i][5]*INV_TAU;
        o1.z = acc[i][6]*INV_TAU; o1.w = acc[i][7]*INV_TAU;
        *(float4*)&g_sims[base]     = o0;
        *(float4*)&g_sims[base + 4] = o1;
    }
}

// ---------------- exact top-k + logsumexp per matched row -----------------------------
// smem: row[8192] | hist[4096] | cand[2048] | red[256] | misc[8]
__global__ void k_select() {
    int bid = blockIdx.x;
    if (bid >= g_cnt) return;
    extern __shared__ float sm[];
    float*    row  = sm;
    int*      hist = (int*)(sm + 8192);
    unsigned* cand = (unsigned*)(sm + 8192 + 4096);
    float*    red  = sm + 8192 + 4096 + 2048;
    int*      misc = (int*)(red + 256);
    int tid = threadIdx.x;
    int srow = g_matched[bid];
    const float* grow = &g_sims[(size_t)bid * NT];

    float lmax = -1e30f;
    #pragma unroll
    for (int i = 0; i < 32; i++) {
        float v = grow[tid + i*256];
        row[tid + i*256] = v;
        lmax = fmaxf(lmax, v);
    }
    red[tid] = lmax;
    __syncthreads();
    for (int s = 128; s > 0; s >>= 1) {
        if (tid < s) red[tid] = fmaxf(red[tid], red[tid + s]);
        __syncthreads();
    }
    float M = red[0];
    __syncthreads();

    for (int i = tid; i < NBINS; i += 256) hist[i] = 0;
    if (tid == 0) misc[3] = 0;
    __syncthreads();
    #pragma unroll
    for (int i = 0; i < 32; i++) {
        float v = row[tid + i*256];
        int b = __float2int_rd((v + 16.0f) * 128.0f);
        b = min(max(b, 0), NBINS - 1);
        atomicAdd(&hist[b], 1);
    }
    __syncthreads();

    // suffix-scan chunk sums (16 bins per thread)
    int cs = 0;
    #pragma unroll
    for (int i = 0; i < 16; i++) cs += hist[tid*16 + i];
    int* ps = (int*)red;
    ps[tid] = cs;
    __syncthreads();
    for (int off = 1; off < 256; off <<= 1) {
        int v = ps[tid] + ((tid + off < 256) ? ps[tid + off] : 0);
        __syncthreads();
        ps[tid] = v;
        __syncthreads();
    }
    int incl = ps[tid];
    int inclNext = (tid < 255) ? ps[tid + 1] : 0;
    if (incl >= KSEL && inclNext < KSEL) {
        int cum = inclNext, B = -1, j = 0;
        for (int b = tid*16 + 15; b >= tid*16; b--) {
            cum += hist[b];
            if (cum >= KSEL) { B = b; j = KSEL - (cum - hist[b]); break; }
        }
        misc[0] = B; misc[1] = j;
    }
    __syncthreads();
    int B = misc[0], j = misc[1];

    // sum exp over bins > B; collect boundary-bin candidates
    float z = 0.f;
    #pragma unroll
    for (int i = 0; i < 32; i++) {
        float v = row[tid + i*256];
        int b = __float2int_rd((v + 16.0f) * 128.0f);
        b = min(max(b, 0), NBINS - 1);
        if (b > B) z += fexp(v - M);
        else if (b == B) {
            int p = atomicAdd(&misc[3], 1);
            if (p < CAND_MAX) cand[p] = okey(v);
        }
    }
    __syncthreads();
    red[tid] = z;
    __syncthreads();
    for (int s = 128; s > 0; s >>= 1) {
        if (tid < s) red[tid] += red[tid + s];
        __syncthreads();
    }
    float Zg = red[0];

    if (tid < 32) {
        int nc = min(misc[3], CAND_MAX);
        // exact j-th largest key among candidates via bisection
        unsigned lo = 0u, hi = 0xFFFFFFFFu;
        while (lo < hi) {
            unsigned mid = lo + ((hi - lo) >> 1) + 1u;
            int c = 0;
            for (int i = tid; i < nc; i += 32) c += (cand[i] >= mid) ? 1 : 0;
            #pragma unroll
            for (int o = 16; o > 0; o >>= 1) c += __shfl_xor_sync(0xffffffffu, c, o);
            if (c >= j) lo = mid; else hi = mid - 1u;
        }
        unsigned theta = lo;
        float zc = 0.f; int ngt = 0;
        for (int i = tid; i < nc; i += 32) {
            unsigned u = cand[i];
            if (u > theta) { ngt++; zc += fexp(kval(u) - M); }
        }
        #pragma unroll
        for (int o = 16; o > 0; o >>= 1) {
            zc  += __shfl_xor_sync(0xffffffffu, zc, o);
            ngt += __shfl_xor_sync(0xffffffffu, ngt, o);
        }
        if (tid == 0) {
            zc += (float)(j - ngt) * fexp(kval(theta) - M);
            float pos = row[g_tidx[srow]];
            float Z = Zg + zc + fexp(pos - M);
            float pp = logf(Z) + M - pos;
            atomicAdd(&g_accum, pp);
        }
    }
}

__global__ void k_final(float* out) {
    if (threadIdx.x == 0) {
        int c = g_cnt;
        float d = (c > 0) ? (float)c : 1.0f;
        out[0] = g_accum / d;
    }
}

// ---------------- launch --------------------------------------------------------------
extern "C" void kernel_launch(void* const* d_in, const int* in_sizes, int n_in,
                              void* d_out, int out_size) {
    const float* tf = (const float*)d_in[0];
    const float* sf = (const float*)d_in[1];
    const float* t_w1 = (const float*)d_in[2];
    const float* t_b1 = (const float*)d_in[3];
    const float* t_w2 = (const float*)d_in[4];
    const float* t_b2 = (const float*)d_in[5];
    const float* t_g  = (const float*)d_in[6];
    const float* t_be = (const float*)d_in[7];
    const float* s_w1 = (const float*)d_in[8];
    const float* s_b1 = (const float*)d_in[9];
    const float* s_w2 = (const float*)d_in[10];
    const float* s_b2 = (const float*)d_in[11];
    const float* s_g  = (const float*)d_in[12];
    const float* s_be = (const float*)d_in[13];
    const int* tco = (const int*)d_in[14];
    const int* sco = (const int*)d_in[15];

    const int SM_PROJ = (16384 + 2048 + 128) * 4;           // 74240
    const int SM_GEMM = 2 * 128 * APAD * 4;                 // 135168
    const int SM_SEL  = (8192 + 4096 + 2048 + 256 + 8) * 4; // 58400
    cudaFuncSetAttribute(k_proj_gemm, cudaFuncAttributeMaxDynamicSharedMemorySize, SM_PROJ);
    cudaFuncSetAttribute(k_gemm,      cudaFuncAttributeMaxDynamicSharedMemorySize, SM_GEMM);
    cudaFuncSetAttribute(k_select,    cudaFuncAttributeMaxDynamicSharedMemorySize, SM_SEL);

    k_init<<<8192, 256>>>();
    k_proj_gemm<<<512, 128, SM_PROJ>>>(tf, 0, t_w1, t_b1, 0, 1);
    k_proj_gemm<<<512, 128, SM_PROJ>>>(nullptr, 1, t_w2, t_b2, 1, 0);
    k_proj_gemm<<<512, 128, SM_PROJ>>>(sf, 0, s_w1, s_b1, 0, 1);
    k_proj_gemm<<<512, 128, SM_PROJ>>>(nullptr, 1, s_w2, s_b2, 2, 0);
    k_bnstat<<<128, 128>>>(0);
    k_bnstat<<<128, 128>>>(1);
    k_bnfinal<<<1, 256>>>(t_g, t_be, s_g, s_be);
    k_norm<<<1024, 256>>>(0);
    k_norm<<<1024, 256>>>(1);
    k_scatter<<<32, 256>>>(tco);
    k_match<<<32, 256>>>(sco);
    dim3 gg(64, 64);
    k_gemm<<<gg, 256, SM_GEMM>>>();
    k_select<<<8192, 256, SM_SEL>>>();
    k_final<<<1, 32>>>((float*)d_out);
}

// round 3
// speedup vs baseline: 1.8885x; 1.8885x over previous
#include <cuda_runtime.h>
#include <cuda_bf16.h>
#include <math.h>
#include <stdint.h>

#define NT 8192
#define NS 8192
#define FD 128
#define KSEL 2457
#define BN_EPS 1e-5f
#define INV_TAU (1.0f/0.07f)
#define NBINS 4096
#define CAND_MAX 2048
#define KEYSPACE (2*64*128*128)

// ---------------- scratch (device globals) --------------------------------------------
__device__ __align__(16) float g_tmp[2][NS*FD];
__device__ __align__(16) float g_h2[2][NS*FD];
__device__ __align__(16) float g_proj[2][NS*FD];
__device__ __align__(16) float g_sims[(size_t)NS*NT];   // 256MB
__device__ __align__(16) __nv_bfloat16 g_Ahi[NS*FD];
__device__ __align__(16) __nv_bfloat16 g_Alo[NS*FD];
__device__ __align__(16) __nv_bfloat16 g_Bhi[NT*FD];
__device__ __align__(16) __nv_bfloat16 g_Blo[NT*FD];
__device__ int   g_keymap[KEYSPACE];   // 0 = empty, else idx+1; restored to 0 each launch
__device__ int   g_matched[NS];
__device__ int   g_tidx[NS];
__device__ int   g_cnt;
__device__ float g_accum;
__device__ float g_bn_sum[2][FD];
__device__ float g_bn_sq[2][FD];
__device__ float g_bn_scale[2][FD];
__device__ float g_bn_shift[2][FD];

// ---------------- helpers ---------------------------------------------------------------
__device__ __forceinline__ uint32_t smem_to_u32(const void* p) {
    uint32_t a;
    asm("{ .reg .u64 t; cvta.to.shared.u64 t, %1; cvt.u32.u64 %0, t; }" : "=r"(a) : "l"(p));
    return a;
}

// fast exp on FFMA pipe (no MUFU)
__device__ __forceinline__ float fexp(float x) {
    float y = x * 1.44269504088896340736f;
    float n = rintf(y);
    float t = (y - n) * 0.69314718055994530942f;
    float p = 1.0f/720.0f;
    p = fmaf(p, t, 1.0f/120.0f);
    p = fmaf(p, t, 1.0f/24.0f);
    p = fmaf(p, t, 1.0f/6.0f);
    p = fmaf(p, t, 0.5f);
    p = fmaf(p, t, 1.0f);
    p = fmaf(p, t, 1.0f);
    int ni = (int)n;
    return p * __int_as_float((ni + 127) << 23);
}
__device__ __forceinline__ unsigned okey(float f) {
    unsigned b = __float_as_uint(f);
    return (b & 0x80000000u) ? ~b : (b | 0x80000000u);
}
__device__ __forceinline__ float kval(unsigned u) {
    unsigned b = (u & 0x80000000u) ? (u & 0x7FFFFFFFu) : ~u;
    return __uint_as_float(b);
}

// ---------------- init ------------------------------------------------------------------
__global__ void k_init() {
    int idx = blockIdx.x * 256 + threadIdx.x;
    if (idx < NS) g_matched[idx] = 0;
    if (idx < 2*FD) {
        ((float*)g_bn_sum)[idx] = 0.f;
        ((float*)g_bn_sq)[idx]  = 0.f;
    }
    if (idx == 0) { g_cnt = 0; g_accum = 0.f; }
}

// ---------------- coord matching ---------------------------------------------------------
__global__ void k_scatter(const int* __restrict__ tc) {
    int i = blockIdx.x * 256 + threadIdx.x;
    if (i >= NT) return;
    int4 c = ((const int4*)tc)[i];
    int key = ((c.x * 64 + c.y) * 128 + c.z) * 128 + c.w;
    g_keymap[key] = i + 1;
}
__global__ void k_match(const int* __restrict__ sc) {
    int j = blockIdx.x * 256 + threadIdx.x;
    if (j >= NS) return;
    int4 c = ((const int4*)sc)[j];
    int key = ((c.x * 64 + c.y) * 128 + c.z) * 128 + c.w;
    int t = g_keymap[key] - 1;
    g_tidx[j] = (t < 0) ? 0 : t;
    if (t >= 0) {
        int p = atomicAdd(&g_cnt, 1);
        g_matched[p] = j;
    }
}
__global__ void k_unscatter(const int* __restrict__ tc) {
    int i = blockIdx.x * 256 + threadIdx.x;
    if (i >= NT) return;
    int4 c = ((const int4*)tc)[i];
    int key = ((c.x * 64 + c.y) * 128 + c.z) * 128 + c.w;
    g_keymap[key] = 0;
}

// ---------------- projection GEMM: 32 rows/CTA, 256 thr, 4x4 micro-tile -----------------
__global__ __launch_bounds__(256) void k_proj(
    const float* __restrict__ tf, const float* __restrict__ sf,
    const float* __restrict__ tw, const float* __restrict__ tb,
    const float* __restrict__ sw, const float* __restrict__ sbias,
    int layer, int relu)
{
    extern __shared__ float sm[];
    float* Ws = sm;             // 128*128
    float* Xs = sm + 16384;     // 32*128
    float* Bs = sm + 20480;     // 128
    int net = blockIdx.z;
    const float* x = layer ? g_tmp[net] : (net ? sf : tf);
    float* out = layer ? g_h2[net] : g_tmp[net];
    const float* w = net ? sw : tw;
    const float* b = net ? sbias : tb;
    int tid = threadIdx.x;
    const float4* w4 = (const float4*)w;
    #pragma unroll
    for (int i = 0; i < 16; i++) ((float4*)Ws)[tid + i*256] = w4[tid + i*256];
    int r0 = blockIdx.x * 32;
    const float4* x4 = (const float4*)(x + (size_t)r0 * FD);
    #pragma unroll
    for (int i = 0; i < 4; i++) ((float4*)Xs)[tid + i*256] = x4[tid + i*256];
    if (tid < 128) Bs[tid] = b[tid];
    __syncthreads();
    int tx = tid & 31, ty = tid >> 5;
    float acc[4][4];
    #pragma unroll
    for (int i = 0; i < 4; i++)
        #pragma unroll
        for (int j = 0; j < 4; j++) acc[i][j] = 0.f;
    #pragma unroll 4
    for (int k = 0; k < 128; k++) {
        float4 wv = ((float4*)Ws)[k*32 + tx];
        #pragma unroll
        for (int r = 0; r < 4; r++) {
            float xv = Xs[(ty*4 + r)*128 + k];
            acc[r][0] = fmaf(xv, wv.x, acc[r][0]);
            acc[r][1] = fmaf(xv, wv.y, acc[r][1]);
            acc[r][2] = fmaf(xv, wv.z, acc[r][2]);
            acc[r][3] = fmaf(xv, wv.w, acc[r][3]);
        }
    }
    #pragma unroll
    for (int r = 0; r < 4; r++) {
        float4 o;
        o.x = acc[r][0] + Bs[tx*4+0];
        o.y = acc[r][1] + Bs[tx*4+1];
        o.z = acc[r][2] + Bs[tx*4+2];
        o.w = acc[r][3] + Bs[tx*4+3];
        if (relu) {
            o.x = fmaxf(o.x, 0.f); o.y = fmaxf(o.y, 0.f);
            o.z = fmaxf(o.z, 0.f); o.w = fmaxf(o.w, 0.f);
        }
        *(float4*)&out[(size_t)(r0 + ty*4 + r)*FD + tx*4] = o;
    }
}

// ---------------- BN stats / finalize / normalize ---------------------------------------
__global__ void k_bnstat() {
    int net = blockIdx.z;
    const float* h = g_h2[net];
    int c = threadIdx.x;
    int r0 = blockIdx.x * 64;
    float s = 0.f, q = 0.f;
    for (int r = 0; r < 64; r++) {
        float v = h[(size_t)(r0 + r)*FD + c];
        s += v; q = fmaf(v, v, q);
    }
    atomicAdd(&g_bn_sum[net][c], s);
    atomicAdd(&g_bn_sq[net][c], q);
}
__global__ void k_bnfinal(const float* __restrict__ tg, const float* __restrict__ tb,
                          const float* __restrict__ sg, const float* __restrict__ sb) {
    int idx = threadIdx.x;
    int net = idx >> 7, c = idx & 127;
    const float* gam = net ? sg : tg;
    const float* bet = net ? sb : tb;
    float mu  = g_bn_sum[net][c] * (1.0f/8192.0f);
    float var = g_bn_sq[net][c]  * (1.0f/8192.0f) - mu*mu;
    float sc  = rsqrtf(var + BN_EPS) * gam[c];
    g_bn_scale[net][c] = sc;
    g_bn_shift[net][c] = bet[c] - mu * sc;
}
__global__ void k_norm() {
    int net = blockIdx.z;
    const float* h = g_h2[net];
    float* p = g_proj[net];
    int w = threadIdx.x >> 5, l = threadIdx.x & 31;
    int r = blockIdx.x * 8 + w;
    float4 v  = *(const float4*)&h[(size_t)r*FD + l*4];
    float4 sc = *(const float4*)&g_bn_scale[net][l*4];
    float4 sh = *(const float4*)&g_bn_shift[net][l*4];
    float4 y;
    y.x = fmaf(v.x, sc.x, sh.x); y.y = fmaf(v.y, sc.y, sh.y);
    y.z = fmaf(v.z, sc.z, sh.z); y.w = fmaf(v.w, sc.w, sh.w);
    float ss = y.x*y.x + y.y*y.y + y.z*y.z + y.w*y.w;
    #pragma unroll
    for (int o = 16; o > 0; o >>= 1) ss += __shfl_xor_sync(0xffffffffu, ss, o);
    float inv = rsqrtf(ss);
    y.x *= inv; y.y *= inv; y.z *= inv; y.w *= inv;
    *(float4*)&p[(size_t)r*FD + l*4] = y;
}

// ---------------- hi/lo bf16 split (+ matched-row gather of student) --------------------
__global__ __launch_bounds__(256) void k_split() {
    int t = blockIdx.x * 256 + threadIdx.x;
    int row = t >> 2, seg = (t & 3) * 32;
    const float* src;
    __nv_bfloat16 *dhi, *dlo;
    if (row < NS) {
        int sr = g_matched[row];
        src = g_proj[1] + (size_t)sr * FD;
        dhi = g_Ahi + (size_t)row * FD;
        dlo = g_Alo + (size_t)row * FD;
    } else {
        int r = row - NS;
        src = g_proj[0] + (size_t)r * FD;
        dhi = g_Bhi + (size_t)r * FD;
        dlo = g_Blo + (size_t)r * FD;
    }
    #pragma unroll
    for (int i = 0; i < 32; i += 8) {
        float4 a = *(const float4*)(src + seg + i);
        float4 b = *(const float4*)(src + seg + i + 4);
        float va[8] = {a.x, a.y, a.z, a.w, b.x, b.y, b.z, b.w};
        uint32_t hi[8], lo[8];
        #pragma unroll
        for (int j = 0; j < 8; j++) {
            __nv_bfloat16 h = __float2bfloat16(va[j]);
            __nv_bfloat16 l = __float2bfloat16(va[j] - __bfloat162float(h));
            hi[j] = (uint32_t)__bfloat16_as_ushort(h);
            lo[j] = (uint32_t)__bfloat16_as_ushort(l);
        }
        uint4 ph, pl;
        ph.x = hi[0] | (hi[1] << 16); ph.y = hi[2] | (hi[3] << 16);
        ph.z = hi[4] | (hi[5] << 16); ph.w = hi[6] | (hi[7] << 16);
        pl.x = lo[0] | (lo[1] << 16); pl.y = lo[2] | (lo[3] << 16);
        pl.z = lo[4] | (lo[5] << 16); pl.w = lo[6] | (lo[7] << 16);
        *(uint4*)(dhi + seg + i) = ph;
        *(uint4*)(dlo + seg + i) = pl;
    }
}

// ---------------- HMMA bf16 hi/lo GEMM: CTA 128x128, K=128, 8 warps ----------------------
// smem: A hi | A lo | B hi | B lo, each 128 rows x 128 bf16 (256B/row), 16B-chunk xor swizzle
#define SM_GEMM (4*32768)

__device__ __forceinline__ void ldm_x4(uint32_t* r, uint32_t addr) {
    asm volatile("ldmatrix.sync.aligned.m8n8.x4.shared.b16 {%0,%1,%2,%3}, [%4];"
        : "=r"(r[0]), "=r"(r[1]), "=r"(r[2]), "=r"(r[3]) : "r"(addr));
}
__device__ __forceinline__ void ldm_x2(uint32_t* r, uint32_t addr) {
    asm volatile("ldmatrix.sync.aligned.m8n8.x2.shared.b16 {%0,%1}, [%2];"
        : "=r"(r[0]), "=r"(r[1]) : "r"(addr));
}
__device__ __forceinline__ void mma_bf16(float* c, const uint32_t* a, const uint32_t* b) {
    asm volatile("mma.sync.aligned.m16n8k16.row.col.f32.bf16.bf16.f32 "
        "{%0,%1,%2,%3}, {%4,%5,%6,%7}, {%8,%9}, {%0,%1,%2,%3};"
        : "+f"(c[0]), "+f"(c[1]), "+f"(c[2]), "+f"(c[3])
        : "r"(a[0]), "r"(a[1]), "r"(a[2]), "r"(a[3]), "r"(b[0]), "r"(b[1]));
}

__global__ __launch_bounds__(256) void k_gemm() {
    if ((int)(blockIdx.y * 128) >= g_cnt) return;
    extern __shared__ char smc[];
    uint32_t sb = smem_to_u32(smc);
    int tid = threadIdx.x;

    // cooperative tile load with swizzle: unit = 16B chunk; layout row*16 + (ch ^ (row&7))
    {
        const uint4* gAhi = (const uint4*)(g_Ahi + (size_t)blockIdx.y * 128 * FD);
        const uint4* gAlo = (const uint4*)(g_Alo + (size_t)blockIdx.y * 128 * FD);
        const uint4* gBhi = (const uint4*)(g_Bhi + (size_t)blockIdx.x * 128 * FD);
        const uint4* gBlo = (const uint4*)(g_Blo + (size_t)blockIdx.x * 128 * FD);
        uint4* s = (uint4*)smc;
        #pragma unroll
        for (int it = 0; it < 8; it++) {
            int idx = tid + it * 256;
            int row = idx >> 4, ch = idx & 15;
            int off = row * 16 + (ch ^ (row & 7));
            s[off]          = gAhi[idx];
            s[off + 2048]   = gAlo[idx];
            s[off + 4096]   = gBhi[idx];
            s[off + 6144]   = gBlo[idx];
        }
    }
    __syncthreads();

    int lane = tid & 31, wid = tid >> 5;
    int wm = wid >> 2, wn = wid & 3;      // warp tile: rows wm*64..+63, cols wn*32..+31

    // lane geometry
    int a_sub   = lane >> 3;
    int a_rowin = (lane & 7) + ((a_sub & 1) << 3);
    int a_cb    = a_sub >> 1;             // chunk +0 / +1
    int b_rowin = lane & 7;
    int b_cb    = (lane >> 3) & 1;

    // precompute per-tile row offsets
    uint32_t aBase[4], bBase[4];
    int aM7[4], bM7[4];
    #pragma unroll
    for (int i = 0; i < 4; i++) {
        int row = wm * 64 + i * 16 + a_rowin;
        aBase[i] = sb + row * 256;
        aM7[i] = row & 7;
        int rn = wn * 32 + i * 8 + b_rowin;
        bBase[i] = sb + 65536 + rn * 256;
        bM7[i] = rn & 7;
    }

    float acc[4][4][4];
    #pragma unroll
    for (int i = 0; i < 4; i++)
        #pragma unroll
        for (int j = 0; j < 4; j++)
            #pragma unroll
            for (int q = 0; q < 4; q++) acc[i][j][q] = 0.f;

    #pragma unroll
    for (int ks = 0; ks < 8; ks++) {
        int k2 = ks * 2;
        uint32_t aH[4][4], aL[4][4], bH[4][2], bL[4][2];
        #pragma unroll
        for (int i = 0; i < 4; i++) {
            uint32_t ad = aBase[i] + (((k2 + a_cb) ^ aM7[i]) << 4);
            ldm_x4(aH[i], ad);
            ldm_x4(aL[i], ad + 32768);
        }
        #pragma unroll
        for (int j = 0; j < 4; j++) {
            uint32_t bd = bBase[j] + (((k2 + b_cb) ^ bM7[j]) << 4);
            ldm_x2(bH[j], bd);
            ldm_x2(bL[j], bd + 32768);
        }
        #pragma unroll
        for (int i = 0; i < 4; i++)
            #pragma unroll
            for (int j = 0; j < 4; j++) {
                mma_bf16(acc[i][j], aH[i], bH[j]);
                mma_bf16(acc[i][j], aH[i], bL[j]);
                mma_bf16(acc[i][j], aL[i], bH[j]);
            }
    }

    // epilogue: direct v2 stores (sectors fully covered by lane quads)
    int g = lane >> 2, t = lane & 3;
    size_t rowbase = (size_t)blockIdx.y * 128 + wm * 64 + g;
    int colbase = blockIdx.x * 128 + wn * 32 + t * 2;
    #pragma unroll
    for (int i = 0; i < 4; i++) {
        #pragma unroll
        for (int j = 0; j < 4; j++) {
            size_t r0 = (rowbase + i*16) * NT + colbase + j*8;
            float2 v0 = make_float2(acc[i][j][0] * INV_TAU, acc[i][j][1] * INV_TAU);
            float2 v1 = make_float2(acc[i][j][2] * INV_TAU, acc[i][j][3] * INV_TAU);
            *(float2*)&g_sims[r0] = v0;
            *(float2*)&g_sims[r0 + (size_t)8 * NT] = v1;
        }
    }
}

// ---------------- exact top-k + logsumexp per matched row -------------------------------
__global__ void k_select() {
    int bid = blockIdx.x;
    if (bid >= g_cnt) return;
    extern __shared__ float sm[];
    float*    row  = sm;
    int*      hist = (int*)(sm + 8192);
    unsigned* cand = (unsigned*)(sm + 8192 + 4096);
    float*    red  = sm + 8192 + 4096 + 2048;
    int*      misc = (int*)(red + 256);
    int tid = threadIdx.x;
    int srow = g_matched[bid];
    const float* grow = &g_sims[(size_t)bid * NT];

    float lmax = -1e30f;
    const float4* g4 = (const float4*)grow;
    #pragma unroll
    for (int i = 0; i < 8; i++) {
        float4 v = g4[tid + i*256];
        *(float4*)&row[(tid + i*256)*4] = v;
        lmax = fmaxf(fmaxf(fmaxf(v.x, v.y), fmaxf(v.z, v.w)), lmax);
    }
    red[tid] = lmax;
    __syncthreads();
    for (int s = 128; s > 0; s >>= 1) {
        if (tid < s) red[tid] = fmaxf(red[tid], red[tid + s]);
        __syncthreads();
    }
    float M = red[0];
    __syncthreads();

    for (int i = tid; i < NBINS; i += 256) hist[i] = 0;
    if (tid == 0) misc[3] = 0;
    __syncthreads();
    #pragma unroll
    for (int i = 0; i < 32; i++) {
        float v = row[tid + i*256];
        int b = __float2int_rd((v + 16.0f) * 128.0f);
        b = min(max(b, 0), NBINS - 1);
        atomicAdd(&hist[b], 1);
    }
    __syncthreads();

    int cs = 0;
    #pragma unroll
    for (int i = 0; i < 16; i++) cs += hist[tid*16 + i];
    int* ps = (int*)red;
    ps[tid] = cs;
    __syncthreads();
    for (int off = 1; off < 256; off <<= 1) {
        int v = ps[tid] + ((tid + off < 256) ? ps[tid + off] : 0);
        __syncthreads();
        ps[tid] = v;
        __syncthreads();
    }
    int incl = ps[tid];
    int inclNext = (tid < 255) ? ps[tid + 1] : 0;
    if (incl >= KSEL && inclNext < KSEL) {
        int cum = inclNext, B = -1, j = 0;
        for (int b = tid*16 + 15; b >= tid*16; b--) {
            cum += hist[b];
            if (cum >= KSEL) { B = b; j = KSEL - (cum - hist[b]); break; }
        }
        misc[0] = B; misc[1] = j;
    }
    __syncthreads();
    int B = misc[0], j = misc[1];

    float z = 0.f;
    #pragma unroll
    for (int i = 0; i < 32; i++) {
        float v = row[tid + i*256];
        int b = __float2int_rd((v + 16.0f) * 128.0f);
        b = min(max(b, 0), NBINS - 1);
        if (b > B) z += fexp(v - M);
        else if (b == B) {
            int p = atomicAdd(&misc[3], 1);
            if (p < CAND_MAX) cand[p] = okey(v);
        }
    }
    __syncthreads();
    red[tid] = z;
    __syncthreads();
    for (int s = 128; s > 0; s >>= 1) {
        if (tid < s) red[tid] += red[tid + s];
        __syncthreads();
    }
    float Zg = red[0];

    if (tid < 32) {
        int nc = min(misc[3], CAND_MAX);
        unsigned lo = 0u, hi = 0xFFFFFFFFu;
        while (lo < hi) {
            unsigned mid = lo + ((hi - lo) >> 1) + 1u;
            int c = 0;
            for (int i = tid; i < nc; i += 32) c += (cand[i] >= mid) ? 1 : 0;
            #pragma unroll
            for (int o = 16; o > 0; o >>= 1) c += __shfl_xor_sync(0xffffffffu, c, o);
            if (c >= j) lo = mid; else hi = mid - 1u;
        }
        unsigned theta = lo;
        float zc = 0.f; int ngt = 0;
        for (int i = tid; i < nc; i += 32) {
            unsigned u = cand[i];
            if (u > theta) { ngt++; zc += fexp(kval(u) - M); }
        }
        #pragma unroll
        for (int o = 16; o > 0; o >>= 1) {
            zc  += __shfl_xor_sync(0xffffffffu, zc, o);
            ngt += __shfl_xor_sync(0xffffffffu, ngt, o);
        }
        if (tid == 0) {
            zc += (float)(j - ngt) * fexp(kval(theta) - M);
            float pos = row[g_tidx[srow]];
            float Z = Zg + zc + fexp(pos - M);
            float pp = logf(Z) + M - pos;
            atomicAdd(&g_accum, pp);
        }
    }
}

__global__ void k_final(float* out) {
    if (threadIdx.x == 0) {
        int c = g_cnt;
        float d = (c > 0) ? (float)c : 1.0f;
        out[0] = g_accum / d;
    }
}

// ---------------- launch ------------------------------------------------------------------
extern "C" void kernel_launch(void* const* d_in, const int* in_sizes, int n_in,
                              void* d_out, int out_size) {
    const float* tf = (const float*)d_in[0];
    const float* sf = (const float*)d_in[1];
    const float* t_w1 = (const float*)d_in[2];
    const float* t_b1 = (const float*)d_in[3];
    const float* t_w2 = (const float*)d_in[4];
    const float* t_b2 = (const float*)d_in[5];
    const float* t_g  = (const float*)d_in[6];
    const float* t_be = (const float*)d_in[7];
    const float* s_w1 = (const float*)d_in[8];
    const float* s_b1 = (const float*)d_in[9];
    const float* s_w2 = (const float*)d_in[10];
    const float* s_b2 = (const float*)d_in[11];
    const float* s_g  = (const float*)d_in[12];
    const float* s_be = (const float*)d_in[13];
    const int* tco = (const int*)d_in[14];
    const int* sco = (const int*)d_in[15];

    const int SM_PROJ = (16384 + 4096 + 128) * 4;           // 82432
    const int SM_SEL  = (8192 + 4096 + 2048 + 256 + 8) * 4; // 58400
    cudaFuncSetAttribute(k_proj,   cudaFuncAttributeMaxDynamicSharedMemorySize, SM_PROJ);
    cudaFuncSetAttribute(k_gemm,   cudaFuncAttributeMaxDynamicSharedMemorySize, SM_GEMM);
    cudaFuncSetAttribute(k_select, cudaFuncAttributeMaxDynamicSharedMemorySize, SM_SEL);

    k_init<<<32, 256>>>();
    k_scatter<<<32, 256>>>(tco);
    k_match<<<32, 256>>>(sco);
    k_unscatter<<<32, 256>>>(tco);
    k_proj<<<dim3(256,1,2), 256, SM_PROJ>>>(tf, sf, t_w1, t_b1, s_w1, s_b1, 0, 1);
    k_proj<<<dim3(256,1,2), 256, SM_PROJ>>>(tf, sf, t_w2, t_b2, s_w2, s_b2, 1, 0);
    k_bnstat<<<dim3(128,1,2), 128>>>();
    k_bnfinal<<<1, 256>>>(t_g, t_be, s_g, s_be);
    k_norm<<<dim3(1024,1,2), 256>>>();
    k_split<<<256, 256>>>();
    k_gemm<<<dim3(64, 64), 256, SM_GEMM>>>();
    k_select<<<8192, 256, SM_SEL>>>();
    k_final<<<1, 32>>>((float*)d_out);
}

// round 4
// speedup vs baseline: 2.6701x; 1.4139x over previous
#include <cuda_runtime.h>
#include <cuda_bf16.h>
#include <math.h>
#include <stdint.h>

#define NT 8192
#define NS 8192
#define FD 128
#define KSEL 2457
#define BN_EPS 1e-5f
#define INV_TAU (1.0f/0.07f)
#define QSCALE (INV_TAU * 2048.0f)
#define INV2048 4.8828125e-4f
#define KEYSPACE (2*64*128*128)

// ---------------- scratch (device globals) --------------------------------------------
__device__ __align__(16) float g_h2[2][NS*FD];
__device__ __align__(16) unsigned short g_simsq[(size_t)NS*NT];  // 128MB; only matched rows used
__device__ __align__(16) __nv_bfloat16 g_Ahi[NS*FD];
__device__ __align__(16) __nv_bfloat16 g_Alo[NS*FD];
__device__ __align__(16) __nv_bfloat16 g_Bhi[NT*FD];
__device__ __align__(16) __nv_bfloat16 g_Blo[NT*FD];
__device__ int   g_keymap[KEYSPACE];   // 0 = empty; restored to 0 by k_unscatter each launch
__device__ int   g_matched[NS];
__device__ int   g_tidx[NS];
__device__ int   g_cnt;
__device__ float g_accum;
__device__ float g_bn_sum[2][FD];
__device__ float g_bn_sq[2][FD];
__device__ float g_bn_scale[2][FD];
__device__ float g_bn_shift[2][FD];

// ---------------- helpers ---------------------------------------------------------------
__device__ __forceinline__ uint32_t smem_to_u32(const void* p) {
    uint32_t a;
    asm("{ .reg .u64 t; cvta.to.shared.u64 t, %1; cvt.u32.u64 %0, t; }" : "=r"(a) : "l"(p));
    return a;
}

// fast exp on FFMA pipe (no MUFU)
__device__ __forceinline__ float fexp(float x) {
    float y = x * 1.44269504088896340736f;
    float n = rintf(y);
    float t = (y - n) * 0.69314718055994530942f;
    float p = 1.0f/720.0f;
    p = fmaf(p, t, 1.0f/120.0f);
    p = fmaf(p, t, 1.0f/24.0f);
    p = fmaf(p, t, 1.0f/6.0f);
    p = fmaf(p, t, 0.5f);
    p = fmaf(p, t, 1.0f);
    p = fmaf(p, t, 1.0f);
    int ni = (int)n;
    return p * __int_as_float((ni + 127) << 23);
}

// ---------------- prep: scatter teacher keys + clear per-launch state --------------------
__global__ void k_prep(const int* __restrict__ tc) {
    int i = blockIdx.x * 256 + threadIdx.x;
    int4 c = ((const int4*)tc)[i];
    int key = ((c.x * 64 + c.y) * 128 + c.z) * 128 + c.w;
    g_keymap[key] = i + 1;
    g_matched[i] = 0;
    if (i < 2*FD) {
        ((float*)g_bn_sum)[i] = 0.f;
        ((float*)g_bn_sq)[i]  = 0.f;
    }
    if (i == 0) { g_cnt = 0; g_accum = 0.f; }
}
__global__ void k_match(const int* __restrict__ sc) {
    int j = blockIdx.x * 256 + threadIdx.x;
    int4 c = ((const int4*)sc)[j];
    int key = ((c.x * 64 + c.y) * 128 + c.z) * 128 + c.w;
    int t = g_keymap[key] - 1;
    g_tidx[j] = (t < 0) ? 0 : t;
    if (t >= 0) {
        int p = atomicAdd(&g_cnt, 1);
        g_matched[p] = j;
    }
}
__global__ void k_unscatter(const int* __restrict__ tc) {
    int i = blockIdx.x * 256 + threadIdx.x;
    int4 c = ((const int4*)tc)[i];
    int key = ((c.x * 64 + c.y) * 128 + c.z) * 128 + c.w;
    g_keymap[key] = 0;
}

// ---------------- fused 2-layer projection MLP + BN partial stats ------------------------
// smem: W1[128x128] | W2[128x128] | X[32x128] | H1[32x128] | B1 | B2 | colS | colQ
#define SMP_W1 0
#define SMP_W2 16384
#define SMP_X  32768
#define SMP_H1 36864
#define SMP_B1 40960
#define SMP_B2 41088
#define SMP_CS 41216
#define SMP_CQ 41344
#define SM_PROJ (41472*4)

__global__ __launch_bounds__(256) void k_proj2(
    const float* __restrict__ tf, const float* __restrict__ sf,
    const float* __restrict__ tw1, const float* __restrict__ tb1,
    const float* __restrict__ tw2, const float* __restrict__ tb2,
    const float* __restrict__ sw1, const float* __restrict__ sb1,
    const float* __restrict__ sw2, const float* __restrict__ sb2)
{
    extern __shared__ float sm[];
    int net = blockIdx.z;
    const float* x  = net ? sf : tf;
    const float* w1 = net ? sw1 : tw1;
    const float* b1 = net ? sb1 : tb1;
    const float* w2 = net ? sw2 : tw2;
    const float* b2 = net ? sb2 : tb2;
    int tid = threadIdx.x;

    #pragma unroll
    for (int i = 0; i < 16; i++) {
        ((float4*)(sm + SMP_W1))[tid + i*256] = ((const float4*)w1)[tid + i*256];
        ((float4*)(sm + SMP_W2))[tid + i*256] = ((const float4*)w2)[tid + i*256];
    }
    int r0 = blockIdx.x * 32;
    const float4* x4 = (const float4*)(x + (size_t)r0 * FD);
    #pragma unroll
    for (int i = 0; i < 4; i++) ((float4*)(sm + SMP_X))[tid + i*256] = x4[tid + i*256];
    if (tid < 128) {
        sm[SMP_B1 + tid] = b1[tid];
        sm[SMP_B2 + tid] = b2[tid];
        sm[SMP_CS + tid] = 0.f;
        sm[SMP_CQ + tid] = 0.f;
    }
    __syncthreads();

    int tx = tid & 31, ty = tid >> 5;
    float acc[4][4];

    // layer 1: relu(x @ w1 + b1) -> H1
    #pragma unroll
    for (int i = 0; i < 4; i++)
        #pragma unroll
        for (int j = 0; j < 4; j++) acc[i][j] = 0.f;
    #pragma unroll 4
    for (int k = 0; k < 128; k++) {
        float4 wv = ((float4*)(sm + SMP_W1))[k*32 + tx];
        #pragma unroll
        for (int r = 0; r < 4; r++) {
            float xv = sm[SMP_X + (ty*4 + r)*128 + k];
            acc[r][0] = fmaf(xv, wv.x, acc[r][0]);
            acc[r][1] = fmaf(xv, wv.y, acc[r][1]);
            acc[r][2] = fmaf(xv, wv.z, acc[r][2]);
            acc[r][3] = fmaf(xv, wv.w, acc[r][3]);
        }
    }
    #pragma unroll
    for (int r = 0; r < 4; r++) {
        float4 o;
        o.x = fmaxf(acc[r][0] + sm[SMP_B1 + tx*4+0], 0.f);
        o.y = fmaxf(acc[r][1] + sm[SMP_B1 + tx*4+1], 0.f);
        o.z = fmaxf(acc[r][2] + sm[SMP_B1 + tx*4+2], 0.f);
        o.w = fmaxf(acc[r][3] + sm[SMP_B1 + tx*4+3], 0.f);
        *(float4*)&sm[SMP_H1 + (ty*4 + r)*128 + tx*4] = o;
    }
    __syncthreads();

    // layer 2: H1 @ w2 + b2 -> g_h2, + BN partial stats
    #pragma unroll
    for (int i = 0; i < 4; i++)
        #pragma unroll
        for (int j = 0; j < 4; j++) acc[i][j] = 0.f;
    #pragma unroll 4
    for (int k = 0; k < 128; k++) {
        float4 wv = ((float4*)(sm + SMP_W2))[k*32 + tx];
        #pragma unroll
        for (int r = 0; r < 4; r++) {
            float xv = sm[SMP_H1 + (ty*4 + r)*128 + k];
            acc[r][0] = fmaf(xv, wv.x, acc[r][0]);
            acc[r][1] = fmaf(xv, wv.y, acc[r][1]);
            acc[r][2] = fmaf(xv, wv.z, acc[r][2]);
            acc[r][3] = fmaf(xv, wv.w, acc[r][3]);
        }
    }
    float* out = g_h2[net];
    float cs[4] = {0.f,0.f,0.f,0.f}, cq[4] = {0.f,0.f,0.f,0.f};
    #pragma unroll
    for (int r = 0; r < 4; r++) {
        float4 o;
        o.x = acc[r][0] + sm[SMP_B2 + tx*4+0];
        o.y = acc[r][1] + sm[SMP_B2 + tx*4+1];
        o.z = acc[r][2] + sm[SMP_B2 + tx*4+2];
        o.w = acc[r][3] + sm[SMP_B2 + tx*4+3];
        cs[0] += o.x; cq[0] = fmaf(o.x, o.x, cq[0]);
        cs[1] += o.y; cq[1] = fmaf(o.y, o.y, cq[1]);
        cs[2] += o.z; cq[2] = fmaf(o.z, o.z, cq[2]);
        cs[3] += o.w; cq[3] = fmaf(o.w, o.w, cq[3]);
        *(float4*)&out[(size_t)(r0 + ty*4 + r)*FD + tx*4] = o;
    }
    #pragma unroll
    for (int c = 0; c < 4; c++) {
        atomicAdd(&sm[SMP_CS + tx*4 + c], cs[c]);
        atomicAdd(&sm[SMP_CQ + tx*4 + c], cq[c]);
    }
    __syncthreads();
    if (tid < 128) {
        atomicAdd(&g_bn_sum[net][tid], sm[SMP_CS + tid]);
        atomicAdd(&g_bn_sq[net][tid],  sm[SMP_CQ + tid]);
    }
}

__global__ void k_bnfinal(const float* __restrict__ tg, const float* __restrict__ tb,
                          const float* __restrict__ sg, const float* __restrict__ sb) {
    int idx = threadIdx.x;
    int net = idx >> 7, c = idx & 127;
    const float* gam = net ? sg : tg;
    const float* bet = net ? sb : tb;
    float mu  = g_bn_sum[net][c] * (1.0f/8192.0f);
    float var = g_bn_sq[net][c]  * (1.0f/8192.0f) - mu*mu;
    float sc  = rsqrtf(var + BN_EPS) * gam[c];
    g_bn_scale[net][c] = sc;
    g_bn_shift[net][c] = bet[c] - mu * sc;
}

// ---------------- fused BN + L2 normalize + hi/lo bf16 split -----------------------------
__global__ void k_normsplit() {
    int net = blockIdx.z;
    const float* h = g_h2[net];
    __nv_bfloat16* dhi = net ? g_Ahi : g_Bhi;   // student -> A, teacher -> B
    __nv_bfloat16* dlo = net ? g_Alo : g_Blo;
    int w = threadIdx.x >> 5, l = threadIdx.x & 31;
    int r = blockIdx.x * 8 + w;
    float4 v  = *(const float4*)&h[(size_t)r*FD + l*4];
    float4 sc = *(const float4*)&g_bn_scale[net][l*4];
    float4 sh = *(const float4*)&g_bn_shift[net][l*4];
    float y[4];
    y[0] = fmaf(v.x, sc.x, sh.x); y[1] = fmaf(v.y, sc.y, sh.y);
    y[2] = fmaf(v.z, sc.z, sh.z); y[3] = fmaf(v.w, sc.w, sh.w);
    float ss = y[0]*y[0] + y[1]*y[1] + y[2]*y[2] + y[3]*y[3];
    #pragma unroll
    for (int o = 16; o > 0; o >>= 1) ss += __shfl_xor_sync(0xffffffffu, ss, o);
    float inv = rsqrtf(ss);
    uint32_t hi[4], lo[4];
    #pragma unroll
    for (int j = 0; j < 4; j++) {
        float yv = y[j] * inv;
        __nv_bfloat16 hb = __float2bfloat16(yv);
        __nv_bfloat16 lb = __float2bfloat16(yv - __bfloat162float(hb));
        hi[j] = (uint32_t)__bfloat16_as_ushort(hb);
        lo[j] = (uint32_t)__bfloat16_as_ushort(lb);
    }
    uint2 ph = make_uint2(hi[0] | (hi[1] << 16), hi[2] | (hi[3] << 16));
    uint2 pl = make_uint2(lo[0] | (lo[1] << 16), lo[2] | (lo[3] << 16));
    *(uint2*)&dhi[(size_t)r*FD + l*4] = ph;
    *(uint2*)&dlo[(size_t)r*FD + l*4] = pl;
}

// ---------------- HMMA bf16 hi/lo GEMM -> int16 sims --------------------------------------
#define SM_GEMM (4*32768)

__device__ __forceinline__ void ldm_x4(uint32_t* r, uint32_t addr) {
    asm volatile("ldmatrix.sync.aligned.m8n8.x4.shared.b16 {%0,%1,%2,%3}, [%4];"
        : "=r"(r[0]), "=r"(r[1]), "=r"(r[2]), "=r"(r[3]) : "r"(addr));
}
__device__ __forceinline__ void ldm_x2(uint32_t* r, uint32_t addr) {
    asm volatile("ldmatrix.sync.aligned.m8n8.x2.shared.b16 {%0,%1}, [%2];"
        : "=r"(r[0]), "=r"(r[1]) : "r"(addr));
}
__device__ __forceinline__ void mma_bf16(float* c, const uint32_t* a, const uint32_t* b) {
    asm volatile("mma.sync.aligned.m16n8k16.row.col.f32.bf16.bf16.f32 "
        "{%0,%1,%2,%3}, {%4,%5,%6,%7}, {%8,%9}, {%0,%1,%2,%3};"
        : "+f"(c[0]), "+f"(c[1]), "+f"(c[2]), "+f"(c[3])
        : "r"(a[0]), "r"(a[1]), "r"(a[2]), "r"(a[3]), "r"(b[0]), "r"(b[1]));
}

__global__ __launch_bounds__(256) void k_gemm() {
    if ((int)(blockIdx.y * 128) >= g_cnt) return;
    extern __shared__ char smc[];
    uint32_t sb = smem_to_u32(smc);
    int tid = threadIdx.x;

    // cooperative tile load with swizzle; A rows gathered via g_matched
    {
        const int* mrow = &g_matched[blockIdx.y * 128];
        const uint4* gBhi = (const uint4*)(g_Bhi + (size_t)blockIdx.x * 128 * FD);
        const uint4* gBlo = (const uint4*)(g_Blo + (size_t)blockIdx.x * 128 * FD);
        uint4* s = (uint4*)smc;
        #pragma unroll
        for (int it = 0; it < 8; it++) {
            int idx = tid + it * 256;
            int row = idx >> 4, ch = idx & 15;
            int off = row * 16 + (ch ^ (row & 7));
            int ar = mrow[row];
            s[off]        = ((const uint4*)(g_Ahi + (size_t)ar * FD))[ch];
            s[off + 2048] = ((const uint4*)(g_Alo + (size_t)ar * FD))[ch];
            s[off + 4096] = gBhi[idx];
            s[off + 6144] = gBlo[idx];
        }
    }
    __syncthreads();

    int lane = tid & 31, wid = tid >> 5;
    int wm = wid >> 2, wn = wid & 3;

    int a_sub   = lane >> 3;
    int a_rowin = (lane & 7) + ((a_sub & 1) << 3);
    int a_cb    = a_sub >> 1;
    int b_rowin = lane & 7;
    int b_cb    = (lane >> 3) & 1;

    uint32_t aBase[4], bBase[4];
    int aM7[4], bM7[4];
    #pragma unroll
    for (int i = 0; i < 4; i++) {
        int row = wm * 64 + i * 16 + a_rowin;
        aBase[i] = sb + row * 256;
        aM7[i] = row & 7;
        int rn = wn * 32 + i * 8 + b_rowin;
        bBase[i] = sb + 65536 + rn * 256;
        bM7[i] = rn & 7;
    }

    float acc[4][4][4];
    #pragma unroll
    for (int i = 0; i < 4; i++)
        #pragma unroll
        for (int j = 0; j < 4; j++)
            #pragma unroll
            for (int q = 0; q < 4; q++) acc[i][j][q] = 0.f;

    #pragma unroll
    for (int ks = 0; ks < 8; ks++) {
        int k2 = ks * 2;
        uint32_t aH[4][4], aL[4][4], bH[4][2], bL[4][2];
        #pragma unroll
        for (int i = 0; i < 4; i++) {
            uint32_t ad = aBase[i] + (((k2 + a_cb) ^ aM7[i]) << 4);
            ldm_x4(aH[i], ad);
            ldm_x4(aL[i], ad + 32768);
        }
        #pragma unroll
        for (int j = 0; j < 4; j++) {
            uint32_t bd = bBase[j] + (((k2 + b_cb) ^ bM7[j]) << 4);
            ldm_x2(bH[j], bd);
            ldm_x2(bL[j], bd + 32768);
        }
        #pragma unroll
        for (int i = 0; i < 4; i++)
            #pragma unroll
            for (int j = 0; j < 4; j++) {
                mma_bf16(acc[i][j], aH[i], bH[j]);
                mma_bf16(acc[i][j], aH[i], bL[j]);
                mma_bf16(acc[i][j], aL[i], bH[j]);
            }
    }

    // epilogue: quantize to int16, pack pairs, store
    int g = lane >> 2, t = lane & 3;
    size_t rowbase = (size_t)blockIdx.y * 128 + wm * 64 + g;
    int colbase = blockIdx.x * 128 + wn * 32 + t * 2;
    #pragma unroll
    for (int i = 0; i < 4; i++) {
        #pragma unroll
        for (int j = 0; j < 4; j++) {
            size_t r0 = (rowbase + i*16) * NT + colbase + j*8;
            int q0 = __float2int_rn(acc[i][j][0] * QSCALE);
            int q1 = __float2int_rn(acc[i][j][1] * QSCALE);
            int q2 = __float2int_rn(acc[i][j][2] * QSCALE);
            int q3 = __float2int_rn(acc[i][j][3] * QSCALE);
            *(uint32_t*)&g_simsq[r0]                 = (q0 & 0xFFFF) | (q1 << 16);
            *(uint32_t*)&g_simsq[r0 + (size_t)8*NT]  = (q2 & 0xFFFF) | (q3 << 16);
        }
    }
}

// ---------------- exact top-k + logsumexp per matched row (int16 domain) ------------------
// smem ints: qrow(4096 = 8192 shorts) | hist(4096) | red(512) | h16(16) | misc(16)
#define SM_SEL ((4096 + 4096 + 512 + 16 + 16)*4)

__global__ __launch_bounds__(512) void k_select() {
    int bid = blockIdx.x;
    if (bid >= g_cnt) return;
    extern __shared__ int sms[];
    int* qrow = sms;              // 8192 shorts viewed as 4096 ints
    int* hist = sms + 4096;
    int* red  = sms + 8192;
    int* h16  = sms + 8704;
    int* misc = sms + 8720;
    int tid = threadIdx.x;

    for (int i = tid; i < 4096; i += 512) hist[i] = 0;
    if (tid < 16) h16[tid] = 0;
    __syncthreads();

    // load 16KB row, build max + histogram in one pass
    const uint4* g4 = (const uint4*)(g_simsq + (size_t)bid * NT);
    int qmax = -131072;
    #pragma unroll
    for (int u = 0; u < 2; u++) {
        uint4 v = g4[tid + u*512];
        ((uint4*)qrow)[tid + u*512] = v;
        uint32_t ws[4] = {v.x, v.y, v.z, v.w};
        #pragma unroll
        for (int p = 0; p < 4; p++) {
            int q0 = (int)(short)(ws[p] & 0xFFFF);
            int q1 = (int)(short)(ws[p] >> 16);
            qmax = max(qmax, max(q0, q1));
            atomicAdd(&hist[(q0 + 32768) >> 4], 1);
            atomicAdd(&hist[(q1 + 32768) >> 4], 1);
        }
    }
    red[tid] = qmax;
    __syncthreads();
    for (int s = 256; s > 0; s >>= 1) {
        if (tid < s) red[tid] = max(red[tid], red[tid + s]);
        __syncthreads();
    }
    qmax = red[0];
    __syncthreads();

    // suffix scan of 8-bin chunks to locate boundary bin B and rank j within it
    int cs = 0;
    #pragma unroll
    for (int i = 0; i < 8; i++) cs += hist[tid*8 + i];
    red[tid] = cs;
    __syncthreads();
    for (int off = 1; off < 512; off <<= 1) {
        int v = red[tid] + ((tid + off < 512) ? red[tid + off] : 0);
        __syncthreads();
        red[tid] = v;
        __syncthreads();
    }
    int incl = red[tid];
    int inclNext = (tid < 511) ? red[tid + 1] : 0;
    if (incl >= KSEL && inclNext < KSEL) {
        int cum = inclNext;
        for (int b = tid*8 + 7; b >= tid*8; b--) {
            cum += hist[b];
            if (cum >= KSEL) { misc[0] = b; misc[1] = KSEL - (cum - hist[b]); break; }
        }
    }
    __syncthreads();
    int B = misc[0], j = misc[1];

    // pass 2: sum exp over bins > B; count boundary-bin value slots (exact, 16 slots/bin)
    float z = 0.f;
    #pragma unroll
    for (int i = 0; i < 8; i++) {
        int w = qrow[tid + i*512];
        int q0 = (int)(short)(w & 0xFFFF);
        int q1 = (int)(short)(w >> 16);
        int b0 = (q0 + 32768) >> 4;
        int b1 = (q1 + 32768) >> 4;
        if (b0 > B) z += fexp((float)(q0 - qmax) * INV2048);
        else if (b0 == B) atomicAdd(&h16[(q0 + 32768) & 15], 1);
        if (b1 > B) z += fexp((float)(q1 - qmax) * INV2048);
        else if (b1 == B) atomicAdd(&h16[(q1 + 32768) & 15], 1);
    }
    __syncthreads();
    float* zred = (float*)red;
    zred[tid] = z;
    __syncthreads();
    for (int s = 256; s > 0; s >>= 1) {
        if (tid < s) zred[tid] += zred[tid + s];
        __syncthreads();
    }

    if (tid == 0) {
        float Z = zred[0];
        // take exactly j elements from boundary bin, highest slots first
        int need = j;
        for (int s = 15; s >= 0 && need > 0; s--) {
            int c = h16[s];
            if (c == 0) continue;
            int take = min(c, need);
            int q = B*16 + s - 32768;
            Z += (float)take * fexp((float)(q - qmax) * INV2048);
            need -= take;
        }
        int srow = g_matched[bid];
        int col = g_tidx[srow];
        int qpos = (int)((short*)qrow)[col];
        Z += fexp((float)(qpos - qmax) * INV2048);
        float pp = logf(Z) + (float)(qmax - qpos) * INV2048;
        atomicAdd(&g_accum, pp);
    }
}

__global__ void k_final(float* out) {
    if (threadIdx.x == 0) {
        int c = g_cnt;
        float d = (c > 0) ? (float)c : 1.0f;
        out[0] = g_accum / d;
    }
}

// ---------------- launch ------------------------------------------------------------------
extern "C" void kernel_launch(void* const* d_in, const int* in_sizes, int n_in,
                              void* d_out, int out_size) {
    const float* tf = (const float*)d_in[0];
    const float* sf = (const float*)d_in[1];
    const float* t_w1 = (const float*)d_in[2];
    const float* t_b1 = (const float*)d_in[3];
    const float* t_w2 = (const float*)d_in[4];
    const float* t_b2 = (const float*)d_in[5];
    const float* t_g  = (const float*)d_in[6];
    const float* t_be = (const float*)d_in[7];
    const float* s_w1 = (const float*)d_in[8];
    const float* s_b1 = (const float*)d_in[9];
    const float* s_w2 = (const float*)d_in[10];
    const float* s_b2 = (const float*)d_in[11];
    const float* s_g  = (const float*)d_in[12];
    const float* s_be = (const float*)d_in[13];
    const int* tco = (const int*)d_in[14];
    const int* sco = (const int*)d_in[15];

    cudaFuncSetAttribute(k_proj2,  cudaFuncAttributeMaxDynamicSharedMemorySize, SM_PROJ);
    cudaFuncSetAttribute(k_gemm,   cudaFuncAttributeMaxDynamicSharedMemorySize, SM_GEMM);
    cudaFuncSetAttribute(k_select, cudaFuncAttributeMaxDynamicSharedMemorySize, SM_SEL);

    k_prep<<<32, 256>>>(tco);                                   // 0
    k_match<<<32, 256>>>(sco);                                  // 1
    k_proj2<<<dim3(256,1,2), 256, SM_PROJ>>>(tf, sf,            // 2
        t_w1, t_b1, t_w2, t_b2, s_w1, s_b1, s_w2, s_b2);
    k_bnfinal<<<1, 256>>>(t_g, t_be, s_g, s_be);                // 3
    k_normsplit<<<dim3(1024,1,2), 256>>>();                     // 4
    k_gemm<<<dim3(64, 64), 256, SM_GEMM>>>();                   // 5  <- ncu -s 5 captures this
    k_select<<<8192, 512, SM_SEL>>>();                          // 6
    k_final<<<1, 32>>>((float*)d_out);                          // 7
    k_unscatter<<<32, 256>>>(tco);                              // 8 (restores keymap for next replay)
}

// round 5
// speedup vs baseline: 3.2702x; 1.2247x over previous
#include <cuda_runtime.h>
#include <cuda_bf16.h>
#include <math.h>
#include <stdint.h>

#define NT 8192
#define NS 8192
#define FD 128
#define KSEL 2457
#define BN_EPS 1e-5f
#define INV_TAU (1.0f/0.07f)
#define QSCALE (INV_TAU * 2048.0f)
#define INV2048 4.8828125e-4f
#define KEYSPACE (2*64*128*128)

// ---------------- scratch (device globals) --------------------------------------------
__device__ __align__(16) float g_h2[2][NS*FD];
__device__ __align__(16) unsigned short g_simsq[(size_t)NS*NT];  // 128MB
__device__ __align__(16) __nv_bfloat16 g_Ahi[NS*FD];
__device__ __align__(16) __nv_bfloat16 g_Alo[NS*FD];
__device__ __align__(16) __nv_bfloat16 g_Bhi[NT*FD];
__device__ __align__(16) __nv_bfloat16 g_Blo[NT*FD];
__device__ __align__(16) uint4 g_wq[2][2][2][2048];  // [net][layer][hi/lo][swizzled chunks]
__device__ int   g_keymap[KEYSPACE];   // 0 = empty; restored by k_fin each launch
__device__ int   g_matched[NS];
__device__ int   g_tidx[NS];
__device__ int   g_cnt;
__device__ float g_accum;
__device__ float g_bn_sum[2][FD];
__device__ float g_bn_sq[2][FD];

// ---------------- helpers ---------------------------------------------------------------
__device__ __forceinline__ uint32_t smem_to_u32(const void* p) {
    uint32_t a;
    asm("{ .reg .u64 t; cvta.to.shared.u64 t, %1; cvt.u32.u64 %0, t; }" : "=r"(a) : "l"(p));
    return a;
}
__device__ __forceinline__ void cp16(uint32_t s, const void* g) {
    asm volatile("cp.async.cg.shared.global [%0], [%1], 16;" :: "r"(s), "l"(g));
}
__device__ __forceinline__ void cp_commit_wait() {
    asm volatile("cp.async.commit_group;");
    asm volatile("cp.async.wait_group 0;");
}
__device__ __forceinline__ void ldm_x4(uint32_t* r, uint32_t addr) {
    asm volatile("ldmatrix.sync.aligned.m8n8.x4.shared.b16 {%0,%1,%2,%3}, [%4];"
        : "=r"(r[0]), "=r"(r[1]), "=r"(r[2]), "=r"(r[3]) : "r"(addr));
}
__device__ __forceinline__ void ldm_x2(uint32_t* r, uint32_t addr) {
    asm volatile("ldmatrix.sync.aligned.m8n8.x2.shared.b16 {%0,%1}, [%2];"
        : "=r"(r[0]), "=r"(r[1]) : "r"(addr));
}
__device__ __forceinline__ void mma_bf16(float* c, const uint32_t* a, const uint32_t* b) {
    asm volatile("mma.sync.aligned.m16n8k16.row.col.f32.bf16.bf16.f32 "
        "{%0,%1,%2,%3}, {%4,%5,%6,%7}, {%8,%9}, {%0,%1,%2,%3};"
        : "+f"(c[0]), "+f"(c[1]), "+f"(c[2]), "+f"(c[3])
        : "r"(a[0]), "r"(a[1]), "r"(a[2]), "r"(a[3]), "r"(b[0]), "r"(b[1]));
}
__device__ __forceinline__ float fexp(float x) {
    float y = x * 1.44269504088896340736f;
    float n = rintf(y);
    float t = (y - n) * 0.69314718055994530942f;
    float p = 1.0f/720.0f;
    p = fmaf(p, t, 1.0f/120.0f);
    p = fmaf(p, t, 1.0f/24.0f);
    p = fmaf(p, t, 1.0f/6.0f);
    p = fmaf(p, t, 0.5f);
    p = fmaf(p, t, 1.0f);
    p = fmaf(p, t, 1.0f);
    int ni = (int)n;
    return p * __int_as_float((ni + 127) << 23);
}
__device__ __forceinline__ uint32_t pack_hi(float a, float b) {
    __nv_bfloat16 h0 = __float2bfloat16(a), h1 = __float2bfloat16(b);
    return (uint32_t)__bfloat16_as_ushort(h0) | ((uint32_t)__bfloat16_as_ushort(h1) << 16);
}
__device__ __forceinline__ uint32_t pack_lo(float a, float b) {
    __nv_bfloat16 h0 = __float2bfloat16(a), h1 = __float2bfloat16(b);
    float r0 = a - __bfloat162float(h0), r1 = b - __bfloat162float(h1);
    __nv_bfloat16 l0 = __float2bfloat16(r0), l1 = __float2bfloat16(r1);
    return (uint32_t)__bfloat16_as_ushort(l0) | ((uint32_t)__bfloat16_as_ushort(l1) << 16);
}

// ---------------- prep: scatter keys + clears + weight transpose/split -------------------
__global__ void k_prep(const int* __restrict__ tc,
                       const float* __restrict__ tw1, const float* __restrict__ tw2,
                       const float* __restrict__ sw1, const float* __restrict__ sw2) {
    int i = blockIdx.x * 256 + threadIdx.x;
    int4 c = ((const int4*)tc)[i];
    int key = ((c.x * 64 + c.y) * 128 + c.z) * 128 + c.w;
    g_keymap[key] = i + 1;
    g_matched[i] = 0;
    if (i < 2*FD) {
        ((float*)g_bn_sum)[i] = 0.f;
        ((float*)g_bn_sq)[i]  = 0.f;
    }
    if (i == 0) { g_cnt = 0; g_accum = 0.f; }

    // weight transpose + hi/lo split + swizzle: 4096 items = net(2) x layer(2) x n(128) x kg(8)
    if (i < 4096) {
        int kg = i & 7, n = (i >> 3) & 127, layer = (i >> 10) & 1, net = i >> 11;
        const float* w = net ? (layer ? sw2 : sw1) : (layer ? tw2 : tw1);
        #pragma unroll
        for (int half = 0; half < 2; half++) {
            int kb = kg * 16 + half * 8;
            uint32_t hw[4], lw[4];
            #pragma unroll
            for (int q = 0; q < 4; q++) {
                float v0 = w[(kb + q*2    ) * 128 + n];
                float v1 = w[(kb + q*2 + 1) * 128 + n];
                hw[q] = pack_hi(v0, v1);
                lw[q] = pack_lo(v0, v1);
            }
            int ch = kg * 2 + half;
            int idx = n * 16 + (ch ^ (n & 7));
            g_wq[net][layer][0][idx] = make_uint4(hw[0], hw[1], hw[2], hw[3]);
            g_wq[net][layer][1][idx] = make_uint4(lw[0], lw[1], lw[2], lw[3]);
        }
    }
}
__global__ void k_match(const int* __restrict__ sc) {
    int j = blockIdx.x * 256 + threadIdx.x;
    int4 c = ((const int4*)sc)[j];
    int key = ((c.x * 64 + c.y) * 128 + c.z) * 128 + c.w;
    int t = g_keymap[key] - 1;
    g_tidx[j] = (t < 0) ? 0 : t;
    if (t >= 0) {
        int p = atomicAdd(&g_cnt, 1);
        g_matched[p] = j;
    }
}

// ---------------- fused 2-layer projection via HMMA hi/lo --------------------------------
// smem bytes: XH 0 | XL 32768 | W1H 65536 | W1L 98304 | W2H 131072 | W2L 163840
//             | BIAS 196608 (256 f) | CS 197632 (128 f) | CQ 198144 (128 f)
#define PJ_XH 0
#define PJ_XL 32768
#define PJ_W1H 65536
#define PJ_W1L 98304
#define PJ_W2H 131072
#define PJ_W2L 163840
#define PJ_BIAS 196608
#define PJ_CS 197632
#define PJ_CQ 198144
#define SM_PROJ 198656

__global__ __launch_bounds__(256) void k_projmma(
    const float* __restrict__ tf, const float* __restrict__ sf,
    const float* __restrict__ tb1, const float* __restrict__ tb2,
    const float* __restrict__ sb1, const float* __restrict__ sb2)
{
    extern __shared__ char smc[];
    uint32_t sb = smem_to_u32(smc);
    float* smf = (float*)smc;
    int net = blockIdx.z;
    const float* x  = net ? sf : tf;
    const float* b1 = net ? sb1 : tb1;
    const float* b2 = net ? sb2 : tb2;
    int tid = threadIdx.x;
    int r0 = blockIdx.x * 128;

    // load X fp32 -> hi/lo bf16 swizzled smem
    #pragma unroll
    for (int it = 0; it < 8; it++) {
        int cidx = tid + it * 256;            // 2048 chunks
        int row = cidx >> 4, ch = cidx & 15;
        const float4* src = (const float4*)(x + (size_t)(r0 + row) * FD + ch * 8);
        float4 f0 = src[0], f1 = src[1];
        uint4 hv, lv;
        hv.x = pack_hi(f0.x, f0.y); lv.x = pack_lo(f0.x, f0.y);
        hv.y = pack_hi(f0.z, f0.w); lv.y = pack_lo(f0.z, f0.w);
        hv.z = pack_hi(f1.x, f1.y); lv.z = pack_lo(f1.x, f1.y);
        hv.w = pack_hi(f1.z, f1.w); lv.w = pack_lo(f1.z, f1.w);
        uint32_t off = (uint32_t)row * 256 + (uint32_t)((ch ^ (row & 7)) << 4);
        *(uint4*)(smc + PJ_XH + off) = hv;
        *(uint4*)(smc + PJ_XL + off) = lv;
    }
    // W tiles (pre-swizzled in gmem)
    #pragma unroll
    for (int it = 0; it < 8; it++) {
        int cidx = tid + it * 256;
        ((uint4*)(smc + PJ_W1H))[cidx] = g_wq[net][0][0][cidx];
        ((uint4*)(smc + PJ_W1L))[cidx] = g_wq[net][0][1][cidx];
        ((uint4*)(smc + PJ_W2H))[cidx] = g_wq[net][1][0][cidx];
        ((uint4*)(smc + PJ_W2L))[cidx] = g_wq[net][1][1][cidx];
    }
    if (tid < 128) {
        smf[PJ_BIAS/4 + tid]       = b1[tid];
        smf[PJ_BIAS/4 + 128 + tid] = b2[tid];
        smf[PJ_CS/4 + tid] = 0.f;
        smf[PJ_CQ/4 + tid] = 0.f;
    }
    __syncthreads();

    int lane = tid & 31, wid = tid >> 5;
    int wm = wid >> 2, wn = wid & 3;
    int a_sub   = lane >> 3;
    int a_rowin = (lane & 7) + ((a_sub & 1) << 3);
    int a_cb    = a_sub >> 1;
    int b_rowin = lane & 7;
    int b_cb    = (lane >> 3) & 1;
    int g = lane >> 2, t = lane & 3;

    uint32_t aBase[4], bBase[4];
    int aM7[4], bM7[4];
    #pragma unroll
    for (int i = 0; i < 4; i++) {
        int row = wm * 64 + i * 16 + a_rowin;
        aBase[i] = sb + PJ_XH + row * 256;
        aM7[i] = row & 7;
        int rn = wn * 32 + i * 8 + b_rowin;
        bBase[i] = sb + rn * 256;     // add W offset at use
        bM7[i] = rn & 7;
    }

    float acc[4][4][4];

    // ---- layer 1 ----
    #pragma unroll
    for (int i = 0; i < 4; i++)
        #pragma unroll
        for (int j = 0; j < 4; j++)
            #pragma unroll
            for (int q = 0; q < 4; q++) acc[i][j][q] = 0.f;
    #pragma unroll
    for (int ks = 0; ks < 8; ks++) {
        int k2 = ks * 2;
        uint32_t aH[4][4], aL[4][4], bH[4][2], bL[4][2];
        #pragma unroll
        for (int i = 0; i < 4; i++) {
            uint32_t ad = aBase[i] + (((k2 + a_cb) ^ aM7[i]) << 4);
            ldm_x4(aH[i], ad);
            ldm_x4(aL[i], ad + 32768);
        }
        #pragma unroll
        for (int j = 0; j < 4; j++) {
            uint32_t bd = bBase[j] + PJ_W1H + (((k2 + b_cb) ^ bM7[j]) << 4);
            ldm_x2(bH[j], bd);
            ldm_x2(bL[j], bd + 32768);
        }
        #pragma unroll
        for (int i = 0; i < 4; i++)
            #pragma unroll
            for (int j = 0; j < 4; j++) {
                mma_bf16(acc[i][j], aH[i], bH[j]);
                mma_bf16(acc[i][j], aH[i], bL[j]);
                mma_bf16(acc[i][j], aL[i], bH[j]);
            }
    }
    __syncthreads();   // all layer-1 reads of X done

    // bias + relu + re-split into XH/XL (now holding H1)
    #pragma unroll
    for (int i = 0; i < 4; i++) {
        #pragma unroll
        for (int j = 0; j < 4; j++) {
            int col0 = wn * 32 + j * 8 + t * 2;
            float bb0 = smf[PJ_BIAS/4 + col0], bb1 = smf[PJ_BIAS/4 + col0 + 1];
            float v0 = fmaxf(acc[i][j][0] + bb0, 0.f);
            float v1 = fmaxf(acc[i][j][1] + bb1, 0.f);
            float v2 = fmaxf(acc[i][j][2] + bb0, 0.f);
            float v3 = fmaxf(acc[i][j][3] + bb1, 0.f);
            int rl = wm * 64 + i * 16 + g, rh = rl + 8;
            uint32_t offl = rl * 256 + (((col0 >> 3) ^ (rl & 7)) << 4) + (col0 & 7) * 2;
            uint32_t offh = rh * 256 + (((col0 >> 3) ^ (rh & 7)) << 4) + (col0 & 7) * 2;
            *(uint32_t*)(smc + PJ_XH + offl) = pack_hi(v0, v1);
            *(uint32_t*)(smc + PJ_XL + offl) = pack_lo(v0, v1);
            *(uint32_t*)(smc + PJ_XH + offh) = pack_hi(v2, v3);
            *(uint32_t*)(smc + PJ_XL + offh) = pack_lo(v2, v3);
        }
    }
    __syncthreads();

    // ---- layer 2 ----
    #pragma unroll
    for (int i = 0; i < 4; i++)
        #pragma unroll
        for (int j = 0; j < 4; j++)
            #pragma unroll
            for (int q = 0; q < 4; q++) acc[i][j][q] = 0.f;
    #pragma unroll
    for (int ks = 0; ks < 8; ks++) {
        int k2 = ks * 2;
        uint32_t aH[4][4], aL[4][4], bH[4][2], bL[4][2];
        #pragma unroll
        for (int i = 0; i < 4; i++) {
            uint32_t ad = aBase[i] + (((k2 + a_cb) ^ aM7[i]) << 4);
            ldm_x4(aH[i], ad);
            ldm_x4(aL[i], ad + 32768);
        }
        #pragma unroll
        for (int j = 0; j < 4; j++) {
            uint32_t bd = bBase[j] + PJ_W2H + (((k2 + b_cb) ^ bM7[j]) << 4);
            ldm_x2(bH[j], bd);
            ldm_x2(bL[j], bd + 32768);
        }
        #pragma unroll
        for (int i = 0; i < 4; i++)
            #pragma unroll
            for (int j = 0; j < 4; j++) {
                mma_bf16(acc[i][j], aH[i], bH[j]);
                mma_bf16(acc[i][j], aH[i], bL[j]);
                mma_bf16(acc[i][j], aL[i], bH[j]);
            }
    }

    // epilogue: bias2 + BN partial stats + store g_h2
    float* out = g_h2[net];
    #pragma unroll
    for (int j = 0; j < 4; j++) {
        int col0 = wn * 32 + j * 8 + t * 2;
        float bb0 = smf[PJ_BIAS/4 + 128 + col0], bb1 = smf[PJ_BIAS/4 + 128 + col0 + 1];
        float s0 = 0.f, q0 = 0.f, s1 = 0.f, q1 = 0.f;
        #pragma unroll
        for (int i = 0; i < 4; i++) {
            float v0 = acc[i][j][0] + bb0;
            float v1 = acc[i][j][1] + bb1;
            float v2 = acc[i][j][2] + bb0;
            float v3 = acc[i][j][3] + bb1;
            int rl = wm * 64 + i * 16 + g, rh = rl + 8;
            *(float2*)&out[(size_t)(r0 + rl) * FD + col0] = make_float2(v0, v1);
            *(float2*)&out[(size_t)(r0 + rh) * FD + col0] = make_float2(v2, v3);
            s0 += v0 + v2; q0 += v0*v0 + v2*v2;
            s1 += v1 + v3; q1 += v1*v1 + v3*v3;
        }
        atomicAdd(&smf[PJ_CS/4 + col0], s0);
        atomicAdd(&smf[PJ_CQ/4 + col0], q0);
        atomicAdd(&smf[PJ_CS/4 + col0 + 1], s1);
        atomicAdd(&smf[PJ_CQ/4 + col0 + 1], q1);
    }
    __syncthreads();
    if (tid < 128) {
        atomicAdd(&g_bn_sum[net][tid], smf[PJ_CS/4 + tid]);
        atomicAdd(&g_bn_sq[net][tid],  smf[PJ_CQ/4 + tid]);
    }
}

// ---------------- fused BNfinal + BN apply + L2 normalize + hi/lo split ------------------
__global__ void k_normsplit(const float* __restrict__ tg, const float* __restrict__ tbe,
                            const float* __restrict__ sg, const float* __restrict__ sbe) {
    int net = blockIdx.z;
    const float* h = g_h2[net];
    const float* gam = net ? sg : tg;
    const float* bet = net ? sbe : tbe;
    __nv_bfloat16* dhi = net ? g_Ahi : g_Bhi;   // student -> A, teacher -> B
    __nv_bfloat16* dlo = net ? g_Alo : g_Blo;
    int w = threadIdx.x >> 5, l = threadIdx.x & 31;
    int r = blockIdx.x * 8 + w;

    float4 su = *(const float4*)&g_bn_sum[net][l*4];
    float4 sq = *(const float4*)&g_bn_sq[net][l*4];
    float4 gm = *(const float4*)&gam[l*4];
    float4 bt = *(const float4*)&bet[l*4];
    float sc[4], sh[4];
    {
        float mu, var;
        mu = su.x*(1.f/8192.f); var = sq.x*(1.f/8192.f) - mu*mu;
        sc[0] = rsqrtf(var + BN_EPS) * gm.x; sh[0] = bt.x - mu * sc[0];
        mu = su.y*(1.f/8192.f); var = sq.y*(1.f/8192.f) - mu*mu;
        sc[1] = rsqrtf(var + BN_EPS) * gm.y; sh[1] = bt.y - mu * sc[1];
        mu = su.z*(1.f/8192.f); var = sq.z*(1.f/8192.f) - mu*mu;
        sc[2] = rsqrtf(var + BN_EPS) * gm.z; sh[2] = bt.z - mu * sc[2];
        mu = su.w*(1.f/8192.f); var = sq.w*(1.f/8192.f) - mu*mu;
        sc[3] = rsqrtf(var + BN_EPS) * gm.w; sh[3] = bt.w - mu * sc[3];
    }
    float4 v = *(const float4*)&h[(size_t)r*FD + l*4];
    float y[4];
    y[0] = fmaf(v.x, sc[0], sh[0]); y[1] = fmaf(v.y, sc[1], sh[1]);
    y[2] = fmaf(v.z, sc[2], sh[2]); y[3] = fmaf(v.w, sc[3], sh[3]);
    float ss = y[0]*y[0] + y[1]*y[1] + y[2]*y[2] + y[3]*y[3];
    #pragma unroll
    for (int o = 16; o > 0; o >>= 1) ss += __shfl_xor_sync(0xffffffffu, ss, o);
    float inv = rsqrtf(ss);
    y[0] *= inv; y[1] *= inv; y[2] *= inv; y[3] *= inv;
    uint2 ph = make_uint2(pack_hi(y[0], y[1]), pack_hi(y[2], y[3]));
    uint2 pl = make_uint2(pack_lo(y[0], y[1]), pack_lo(y[2], y[3]));
    *(uint2*)&dhi[(size_t)r*FD + l*4] = ph;
    *(uint2*)&dlo[(size_t)r*FD + l*4] = pl;
}

// ---------------- HMMA bf16 hi/lo GEMM, K streamed in 2 phases, cp.async -----------------
// smem per phase: AH 0 (16KB) | AL 16384 | BH 32768 | BL 49152  (row stride 128B)
#define SM_GEMM 65536

__global__ __launch_bounds__(256, 2) void k_gemm() {
    if ((int)(blockIdx.y * 128) >= g_cnt) return;
    extern __shared__ char smc[];
    uint32_t sb = smem_to_u32(smc);
    int tid = threadIdx.x, lane = tid & 31, wid = tid >> 5;
    int wm = wid >> 2, wn = wid & 3;
    const int* mrow = &g_matched[blockIdx.y * 128];

    int a_sub   = lane >> 3;
    int a_rowin = (lane & 7) + ((a_sub & 1) << 3);
    int a_cb    = a_sub >> 1;
    int b_rowin = lane & 7;
    int b_cb    = (lane >> 3) & 1;

    uint32_t aBase[4], bBase[4];
    int aM7[4], bM7[4];
    #pragma unroll
    for (int i = 0; i < 4; i++) {
        int row = wm * 64 + i * 16 + a_rowin;
        aBase[i] = sb + row * 128;
        aM7[i] = row & 7;
        int rn = wn * 32 + i * 8 + b_rowin;
        bBase[i] = sb + 32768 + rn * 128;
        bM7[i] = rn & 7;
    }

    float acc[4][4][4];
    #pragma unroll
    for (int i = 0; i < 4; i++)
        #pragma unroll
        for (int j = 0; j < 4; j++)
            #pragma unroll
            for (int q = 0; q < 4; q++) acc[i][j][q] = 0.f;

    #pragma unroll
    for (int ph = 0; ph < 2; ph++) {
        // async load of this K-half (64 cols = 8 chunks/row)
        #pragma unroll
        for (int it = 0; it < 4; it++) {
            int idx = tid + it * 256;          // 1024
            int row = idx >> 3, ch = idx & 7;
            uint32_t off = (uint32_t)row * 128 + (uint32_t)((ch ^ (row & 7)) << 4);
            int gc = ch + ph * 8;
            int ar = __ldg(&mrow[row]);
            cp16(sb + off,          (const uint4*)(g_Ahi + (size_t)ar * FD) + gc);
            cp16(sb + 16384 + off,  (const uint4*)(g_Alo + (size_t)ar * FD) + gc);
            size_t br = (size_t)(blockIdx.x * 128 + row) * FD;
            cp16(sb + 32768 + off,  (const uint4*)(g_Bhi + br) + gc);
            cp16(sb + 49152 + off,  (const uint4*)(g_Blo + br) + gc);
        }
        cp_commit_wait();
        __syncthreads();

        #pragma unroll
        for (int ks = 0; ks < 4; ks++) {
            int k2 = ks * 2;
            uint32_t aH[4][4], aL[4][4], bH[4][2], bL[4][2];
            #pragma unroll
            for (int i = 0; i < 4; i++) {
                uint32_t ad = aBase[i] + (((k2 + a_cb) ^ aM7[i]) << 4);
                ldm_x4(aH[i], ad);
                ldm_x4(aL[i], ad + 16384);
            }
            #pragma unroll
            for (int j = 0; j < 4; j++) {
                uint32_t bd = bBase[j] + (((k2 + b_cb) ^ bM7[j]) << 4);
                ldm_x2(bH[j], bd);
                ldm_x2(bL[j], bd + 16384);
            }
            #pragma unroll
            for (int i = 0; i < 4; i++)
                #pragma unroll
                for (int j = 0; j < 4; j++) {
                    mma_bf16(acc[i][j], aH[i], bH[j]);
                    mma_bf16(acc[i][j], aH[i], bL[j]);
                    mma_bf16(acc[i][j], aL[i], bH[j]);
                }
        }
        __syncthreads();   // before overwriting buffers in next phase
    }

    // epilogue: quantize to int16, pack pairs, store
    int g = lane >> 2, t = lane & 3;
    size_t rowbase = (size_t)blockIdx.y * 128 + wm * 64 + g;
    int colbase = blockIdx.x * 128 + wn * 32 + t * 2;
    #pragma unroll
    for (int i = 0; i < 4; i++) {
        #pragma unroll
        for (int j = 0; j < 4; j++) {
            size_t r0 = (rowbase + i*16) * NT + colbase + j*8;
            int q0 = __float2int_rn(acc[i][j][0] * QSCALE);
            int q1 = __float2int_rn(acc[i][j][1] * QSCALE);
            int q2 = __float2int_rn(acc[i][j][2] * QSCALE);
            int q3 = __float2int_rn(acc[i][j][3] * QSCALE);
            *(uint32_t*)&g_simsq[r0]                 = (q0 & 0xFFFF) | (q1 << 16);
            *(uint32_t*)&g_simsq[r0 + (size_t)8*NT]  = (q2 & 0xFFFF) | (q3 << 16);
        }
    }
}

// ---------------- exact top-k + logsumexp per matched row (int16 domain) ------------------
#define SM_SEL ((4096 + 4096 + 512 + 16 + 16)*4)

__global__ __launch_bounds__(512) void k_select() {
    int bid = blockIdx.x;
    if (bid >= g_cnt) return;
    extern __shared__ int sms[];
    int* qrow = sms;
    int* hist = sms + 4096;
    int* red  = sms + 8192;
    int* h16  = sms + 8704;
    int* misc = sms + 8720;
    int tid = threadIdx.x;

    for (int i = tid; i < 4096; i += 512) hist[i] = 0;
    if (tid < 16) h16[tid] = 0;
    __syncthreads();

    const uint4* g4 = (const uint4*)(g_simsq + (size_t)bid * NT);
    int qmax = -131072;
    #pragma unroll
    for (int u = 0; u < 2; u++) {
        uint4 v = g4[tid + u*512];
        ((uint4*)qrow)[tid + u*512] = v;
        uint32_t ws[4] = {v.x, v.y, v.z, v.w};
        #pragma unroll
        for (int p = 0; p < 4; p++) {
            int q0 = (int)(short)(ws[p] & 0xFFFF);
            int q1 = (int)(short)(ws[p] >> 16);
            qmax = max(qmax, max(q0, q1));
            atomicAdd(&hist[(q0 + 32768) >> 4], 1);
            atomicAdd(&hist[(q1 + 32768) >> 4], 1);
        }
    }
    red[tid] = qmax;
    __syncthreads();
    for (int s = 256; s > 0; s >>= 1) {
        if (tid < s) red[tid] = max(red[tid], red[tid + s]);
        __syncthreads();
    }
    qmax = red[0];
    __syncthreads();

    int cs = 0;
    #pragma unroll
    for (int i = 0; i < 8; i++) cs += hist[tid*8 + i];
    red[tid] = cs;
    __syncthreads();
    for (int off = 1; off < 512; off <<= 1) {
        int v = red[tid] + ((tid + off < 512) ? red[tid + off] : 0);
        __syncthreads();
        red[tid] = v;
        __syncthreads();
    }
    int incl = red[tid];
    int inclNext = (tid < 511) ? red[tid + 1] : 0;
    if (incl >= KSEL && inclNext < KSEL) {
        int cum = inclNext;
        for (int b = tid*8 + 7; b >= tid*8; b--) {
            cum += hist[b];
            if (cum >= KSEL) { misc[0] = b; misc[1] = KSEL - (cum - hist[b]); break; }
        }
    }
    __syncthreads();
    int B = misc[0], j = misc[1];

    float z = 0.f;
    #pragma unroll
    for (int i = 0; i < 8; i++) {
        int w = qrow[tid + i*512];
        int q0 = (int)(short)(w & 0xFFFF);
        int q1 = (int)(short)(w >> 16);
        int b0 = (q0 + 32768) >> 4;
        int b1 = (q1 + 32768) >> 4;
        if (b0 > B) z += fexp((float)(q0 - qmax) * INV2048);
        else if (b0 == B) atomicAdd(&h16[(q0 + 32768) & 15], 1);
        if (b1 > B) z += fexp((float)(q1 - qmax) * INV2048);
        else if (b1 == B) atomicAdd(&h16[(q1 + 32768) & 15], 1);
    }
    __syncthreads();
    float* zred = (float*)red;
    zred[tid] = z;
    __syncthreads();
    for (int s = 256; s > 0; s >>= 1) {
        if (tid < s) zred[tid] += zred[tid + s];
        __syncthreads();
    }

    if (tid == 0) {
        float Z = zred[0];
        int need = j;
        for (int s = 15; s >= 0 && need > 0; s--) {
            int c = h16[s];
            if (c == 0) continue;
            int take = min(c, need);
            int q = B*16 + s - 32768;
            Z += (float)take * fexp((float)(q - qmax) * INV2048);
            need -= take;
        }
        int srow = g_matched[bid];
        int col = g_tidx[srow];
        int qpos = (int)((short*)qrow)[col];
        Z += fexp((float)(qpos - qmax) * INV2048);
        float pp = logf(Z) + (float)(qmax - qpos) * INV2048;
        atomicAdd(&g_accum, pp);
    }
}

// ---------------- finalize + keymap restore -----------------------------------------------
__global__ void k_fin(const int* __restrict__ tc, float* out) {
    int i = blockIdx.x * 256 + threadIdx.x;
    int4 c = ((const int4*)tc)[i];
    int key = ((c.x * 64 + c.y) * 128 + c.z) * 128 + c.w;
    g_keymap[key] = 0;
    if (i == 0) {
        int cnt = g_cnt;
        float d = (cnt > 0) ? (float)cnt : 1.0f;
        out[0] = g_accum / d;
    }
}

// ---------------- launch ------------------------------------------------------------------
extern "C" void kernel_launch(void* const* d_in, const int* in_sizes, int n_in,
                              void* d_out, int out_size) {
    const float* tf = (const float*)d_in[0];
    const float* sf = (const float*)d_in[1];
    const float* t_w1 = (const float*)d_in[2];
    const float* t_b1 = (const float*)d_in[3];
    const float* t_w2 = (const float*)d_in[4];
    const float* t_b2 = (const float*)d_in[5];
    const float* t_g  = (const float*)d_in[6];
    const float* t_be = (const float*)d_in[7];
    const float* s_w1 = (const float*)d_in[8];
    const float* s_b1 = (const float*)d_in[9];
    const float* s_w2 = (const float*)d_in[10];
    const float* s_b2 = (const float*)d_in[11];
    const float* s_g  = (const float*)d_in[12];
    const float* s_be = (const float*)d_in[13];
    const int* tco = (const int*)d_in[14];
    const int* sco = (const int*)d_in[15];

    cudaFuncSetAttribute(k_projmma, cudaFuncAttributeMaxDynamicSharedMemorySize, SM_PROJ);
    cudaFuncSetAttribute(k_gemm,    cudaFuncAttributeMaxDynamicSharedMemorySize, SM_GEMM);
    cudaFuncSetAttribute(k_select,  cudaFuncAttributeMaxDynamicSharedMemorySize, SM_SEL);

    k_prep<<<32, 256>>>(tco, t_w1, t_w2, s_w1, s_w2);           // 0
    k_match<<<32, 256>>>(sco);                                  // 1
    k_projmma<<<dim3(64,1,2), 256, SM_PROJ>>>(tf, sf,           // 2
        t_b1, t_b2, s_b1, s_b2);
    k_normsplit<<<dim3(1024,1,2), 256>>>(t_g, t_be, s_g, s_be); // 3
    k_gemm<<<dim3(64, 64), 256, SM_GEMM>>>();                   // 4
    k_select<<<8192, 512, SM_SEL>>>();                          // 5
    k_fin<<<32, 256>>>(tco, (float*)d_out);                     // 6
}

// round 6
// speedup vs baseline: 3.3206x; 1.0154x over previous
#include <cuda_runtime.h>
#include <cuda_bf16.h>
#include <cuda_fp16.h>
#include <math.h>
#include <stdint.h>

#define NT 8192
#define NS 8192
#define FD 128
#define KSEL 2457
#define BN_EPS 1e-5f
#define INV_TAU (1.0f/0.07f)
#define QSCALE (INV_TAU * 2048.0f)
#define INV2048 4.8828125e-4f
#define KEYSPACE (2*64*128*128)

// ---------------- scratch (device globals) --------------------------------------------
__device__ __align__(16) float g_h2[2][NS*FD];
__device__ __align__(16) unsigned short g_simsq[(size_t)NS*NT];  // 128MB
__device__ __align__(16) __half g_Ah[NS*FD];   // student projections, fp16
__device__ __align__(16) __half g_Bh[NT*FD];   // teacher projections, fp16
__device__ __align__(16) uint4 g_wq[2][2][2][2048];  // [net][layer][hi/lo] swizzled bf16 chunks
__device__ int   g_keymap[KEYSPACE];   // 0 = empty; restored by k_fin each launch
__device__ int   g_matched[NS];
__device__ int   g_tidx[NS];
__device__ int   g_cnt;
__device__ float g_accum;
__device__ float g_bn_sum[2][FD];
__device__ float g_bn_sq[2][FD];

// ---------------- helpers ---------------------------------------------------------------
__device__ __forceinline__ uint32_t smem_to_u32(const void* p) {
    uint32_t a;
    asm("{ .reg .u64 t; cvta.to.shared.u64 t, %1; cvt.u32.u64 %0, t; }" : "=r"(a) : "l"(p));
    return a;
}
__device__ __forceinline__ void cp16(uint32_t s, const void* g) {
    asm volatile("cp.async.cg.shared.global [%0], [%1], 16;" :: "r"(s), "l"(g));
}
__device__ __forceinline__ void cp_commit_wait() {
    asm volatile("cp.async.commit_group;");
    asm volatile("cp.async.wait_group 0;");
}
__device__ __forceinline__ void ldm_x4(uint32_t* r, uint32_t addr) {
    asm volatile("ldmatrix.sync.aligned.m8n8.x4.shared.b16 {%0,%1,%2,%3}, [%4];"
        : "=r"(r[0]), "=r"(r[1]), "=r"(r[2]), "=r"(r[3]) : "r"(addr));
}
__device__ __forceinline__ void ldm_x2(uint32_t* r, uint32_t addr) {
    asm volatile("ldmatrix.sync.aligned.m8n8.x2.shared.b16 {%0,%1}, [%2];"
        : "=r"(r[0]), "=r"(r[1]) : "r"(addr));
}
__device__ __forceinline__ void mma_bf16(float* c, const uint32_t* a, const uint32_t* b) {
    asm volatile("mma.sync.aligned.m16n8k16.row.col.f32.bf16.bf16.f32 "
        "{%0,%1,%2,%3}, {%4,%5,%6,%7}, {%8,%9}, {%0,%1,%2,%3};"
        : "+f"(c[0]), "+f"(c[1]), "+f"(c[2]), "+f"(c[3])
        : "r"(a[0]), "r"(a[1]), "r"(a[2]), "r"(a[3]), "r"(b[0]), "r"(b[1]));
}
__device__ __forceinline__ void mma_f16(float* c, const uint32_t* a, const uint32_t* b) {
    asm volatile("mma.sync.aligned.m16n8k16.row.col.f32.f16.f16.f32 "
        "{%0,%1,%2,%3}, {%4,%5,%6,%7}, {%8,%9}, {%0,%1,%2,%3};"
        : "+f"(c[0]), "+f"(c[1]), "+f"(c[2]), "+f"(c[3])
        : "r"(a[0]), "r"(a[1]), "r"(a[2]), "r"(a[3]), "r"(b[0]), "r"(b[1]));
}
__device__ __forceinline__ float fexp(float x) {
    float y = x * 1.44269504088896340736f;
    float n = rintf(y);
    float t = (y - n) * 0.69314718055994530942f;
    float p = 1.0f/720.0f;
    p = fmaf(p, t, 1.0f/120.0f);
    p = fmaf(p, t, 1.0f/24.0f);
    p = fmaf(p, t, 1.0f/6.0f);
    p = fmaf(p, t, 0.5f);
    p = fmaf(p, t, 1.0f);
    p = fmaf(p, t, 1.0f);
    int ni = (int)n;
    return p * __int_as_float((ni + 127) << 23);
}
__device__ __forceinline__ uint32_t pack_hi(float a, float b) {
    __nv_bfloat16 h0 = __float2bfloat16(a), h1 = __float2bfloat16(b);
    return (uint32_t)__bfloat16_as_ushort(h0) | ((uint32_t)__bfloat16_as_ushort(h1) << 16);
}
__device__ __forceinline__ uint32_t pack_lo(float a, float b) {
    __nv_bfloat16 h0 = __float2bfloat16(a), h1 = __float2bfloat16(b);
    float r0 = a - __bfloat162float(h0), r1 = b - __bfloat162float(h1);
    __nv_bfloat16 l0 = __float2bfloat16(r0), l1 = __float2bfloat16(r1);
    return (uint32_t)__bfloat16_as_ushort(l0) | ((uint32_t)__bfloat16_as_ushort(l1) << 16);
}

// ---------------- prep: scatter keys + clears + weight transpose/split -------------------
__global__ void k_prep(const int* __restrict__ tc,
                       const float* __restrict__ tw1, const float* __restrict__ tw2,
                       const float* __restrict__ sw1, const float* __restrict__ sw2) {
    int i = blockIdx.x * 256 + threadIdx.x;
    int4 c = ((const int4*)tc)[i];
    int key = ((c.x * 64 + c.y) * 128 + c.z) * 128 + c.w;
    g_keymap[key] = i + 1;
    g_matched[i] = 0;
    if (i < 2*FD) {
        ((float*)g_bn_sum)[i] = 0.f;
        ((float*)g_bn_sq)[i]  = 0.f;
    }
    if (i == 0) { g_cnt = 0; g_accum = 0.f; }

    if (i < 4096) {
        int kg = i & 7, n = (i >> 3) & 127, layer = (i >> 10) & 1, net = i >> 11;
        const float* w = net ? (layer ? sw2 : sw1) : (layer ? tw2 : tw1);
        #pragma unroll
        for (int half = 0; half < 2; half++) {
            int kb = kg * 16 + half * 8;
            uint32_t hw[4], lw[4];
            #pragma unroll
            for (int q = 0; q < 4; q++) {
                float v0 = w[(kb + q*2    ) * 128 + n];
                float v1 = w[(kb + q*2 + 1) * 128 + n];
                hw[q] = pack_hi(v0, v1);
                lw[q] = pack_lo(v0, v1);
            }
            int ch = kg * 2 + half;
            int idx = n * 16 + (ch ^ (n & 7));
            g_wq[net][layer][0][idx] = make_uint4(hw[0], hw[1], hw[2], hw[3]);
            g_wq[net][layer][1][idx] = make_uint4(lw[0], lw[1], lw[2], lw[3]);
        }
    }
}

// ---------------- fused 2-layer projection via HMMA hi/lo (+ coord match in CTA 0) -------
#define PJ_XH 0
#define PJ_XL 32768
#define PJ_W1H 65536
#define PJ_W1L 98304
#define PJ_W2H 131072
#define PJ_W2L 163840
#define PJ_BIAS 196608
#define PJ_CS 197632
#define PJ_CQ 198144
#define SM_PROJ 198656

__global__ __launch_bounds__(256) void k_projmma(
    const float* __restrict__ tf, const float* __restrict__ sf,
    const float* __restrict__ tb1, const float* __restrict__ tb2,
    const float* __restrict__ sb1, const float* __restrict__ sb2,
    const int* __restrict__ sco)
{
    extern __shared__ char smc[];
    uint32_t sb = smem_to_u32(smc);
    float* smf = (float*)smc;
    int net = blockIdx.z;
    const float* x  = net ? sf : tf;
    const float* b1 = net ? sb1 : tb1;
    const float* b2 = net ? sb2 : tb2;
    int tid = threadIdx.x;
    int r0 = blockIdx.x * 128;

    // CTA (0, net=0): coordinate matching (keymap scattered by k_prep)
    if (blockIdx.x == 0 && net == 0) {
        for (int j0 = tid; j0 < NS; j0 += 256) {
            int4 c = ((const int4*)sco)[j0];
            int key = ((c.x * 64 + c.y) * 128 + c.z) * 128 + c.w;
            int t = g_keymap[key] - 1;
            g_tidx[j0] = (t < 0) ? 0 : t;
            unsigned m = __ballot_sync(0xffffffffu, t >= 0);
            int base = 0;
            if ((tid & 31) == 0) base = atomicAdd(&g_cnt, __popc(m));
            base = __shfl_sync(0xffffffffu, base, 0);
            if (t >= 0) {
                int rank = __popc(m & ((1u << (tid & 31)) - 1u));
                g_matched[base + rank] = j0;
            }
        }
    }

    // load X fp32 -> hi/lo bf16 swizzled smem
    #pragma unroll
    for (int it = 0; it < 8; it++) {
        int cidx = tid + it * 256;
        int row = cidx >> 4, ch = cidx & 15;
        const float4* src = (const float4*)(x + (size_t)(r0 + row) * FD + ch * 8);
        float4 f0 = src[0], f1 = src[1];
        uint4 hv, lv;
        hv.x = pack_hi(f0.x, f0.y); lv.x = pack_lo(f0.x, f0.y);
        hv.y = pack_hi(f0.z, f0.w); lv.y = pack_lo(f0.z, f0.w);
        hv.z = pack_hi(f1.x, f1.y); lv.z = pack_lo(f1.x, f1.y);
        hv.w = pack_hi(f1.z, f1.w); lv.w = pack_lo(f1.z, f1.w);
        uint32_t off = (uint32_t)row * 256 + (uint32_t)((ch ^ (row & 7)) << 4);
        *(uint4*)(smc + PJ_XH + off) = hv;
        *(uint4*)(smc + PJ_XL + off) = lv;
    }
    #pragma unroll
    for (int it = 0; it < 8; it++) {
        int cidx = tid + it * 256;
        ((uint4*)(smc + PJ_W1H))[cidx] = g_wq[net][0][0][cidx];
        ((uint4*)(smc + PJ_W1L))[cidx] = g_wq[net][0][1][cidx];
        ((uint4*)(smc + PJ_W2H))[cidx] = g_wq[net][1][0][cidx];
        ((uint4*)(smc + PJ_W2L))[cidx] = g_wq[net][1][1][cidx];
    }
    if (tid < 128) {
        smf[PJ_BIAS/4 + tid]       = b1[tid];
        smf[PJ_BIAS/4 + 128 + tid] = b2[tid];
        smf[PJ_CS/4 + tid] = 0.f;
        smf[PJ_CQ/4 + tid] = 0.f;
    }
    __syncthreads();

    int lane = tid & 31, wid = tid >> 5;
    int wm = wid >> 2, wn = wid & 3;
    int a_sub   = lane >> 3;
    int a_rowin = (lane & 7) + ((a_sub & 1) << 3);
    int a_cb    = a_sub >> 1;
    int b_rowin = lane & 7;
    int b_cb    = (lane >> 3) & 1;
    int g = lane >> 2, t = lane & 3;

    uint32_t aBase[4], bBase[4];
    int aM7[4], bM7[4];
    #pragma unroll
    for (int i = 0; i < 4; i++) {
        int row = wm * 64 + i * 16 + a_rowin;
        aBase[i] = sb + PJ_XH + row * 256;
        aM7[i] = row & 7;
        int rn = wn * 32 + i * 8 + b_rowin;
        bBase[i] = sb + rn * 256;
        bM7[i] = rn & 7;
    }

    float acc[4][4][4];

    // ---- layer 1 ----
    #pragma unroll
    for (int i = 0; i < 4; i++)
        #pragma unroll
        for (int j = 0; j < 4; j++)
            #pragma unroll
            for (int q = 0; q < 4; q++) acc[i][j][q] = 0.f;
    #pragma unroll
    for (int ks = 0; ks < 8; ks++) {
        int k2 = ks * 2;
        uint32_t aH[4][4], aL[4][4], bH[4][2], bL[4][2];
        #pragma unroll
        for (int i = 0; i < 4; i++) {
            uint32_t ad = aBase[i] + (((k2 + a_cb) ^ aM7[i]) << 4);
            ldm_x4(aH[i], ad);
            ldm_x4(aL[i], ad + 32768);
        }
        #pragma unroll
        for (int j = 0; j < 4; j++) {
            uint32_t bd = bBase[j] + PJ_W1H + (((k2 + b_cb) ^ bM7[j]) << 4);
            ldm_x2(bH[j], bd);
            ldm_x2(bL[j], bd + 32768);
        }
        #pragma unroll
        for (int i = 0; i < 4; i++)
            #pragma unroll
            for (int j = 0; j < 4; j++) {
                mma_bf16(acc[i][j], aH[i], bH[j]);
                mma_bf16(acc[i][j], aH[i], bL[j]);
                mma_bf16(acc[i][j], aL[i], bH[j]);
            }
    }
    __syncthreads();

    // bias + relu + re-split into XH/XL (now H1)
    #pragma unroll
    for (int i = 0; i < 4; i++) {
        #pragma unroll
        for (int j = 0; j < 4; j++) {
            int col0 = wn * 32 + j * 8 + t * 2;
            float bb0 = smf[PJ_BIAS/4 + col0], bb1 = smf[PJ_BIAS/4 + col0 + 1];
            float v0 = fmaxf(acc[i][j][0] + bb0, 0.f);
            float v1 = fmaxf(acc[i][j][1] + bb1, 0.f);
            float v2 = fmaxf(acc[i][j][2] + bb0, 0.f);
            float v3 = fmaxf(acc[i][j][3] + bb1, 0.f);
            int rl = wm * 64 + i * 16 + g, rh = rl + 8;
            uint32_t offl = rl * 256 + (((col0 >> 3) ^ (rl & 7)) << 4) + (col0 & 7) * 2;
            uint32_t offh = rh * 256 + (((col0 >> 3) ^ (rh & 7)) << 4) + (col0 & 7) * 2;
            *(uint32_t*)(smc + PJ_XH + offl) = pack_hi(v0, v1);
            *(uint32_t*)(smc + PJ_XL + offl) = pack_lo(v0, v1);
            *(uint32_t*)(smc + PJ_XH + offh) = pack_hi(v2, v3);
            *(uint32_t*)(smc + PJ_XL + offh) = pack_lo(v2, v3);
        }
    }
    __syncthreads();

    // ---- layer 2 ----
    #pragma unroll
    for (int i = 0; i < 4; i++)
        #pragma unroll
        for (int j = 0; j < 4; j++)
            #pragma unroll
            for (int q = 0; q < 4; q++) acc[i][j][q] = 0.f;
    #pragma unroll
    for (int ks = 0; ks < 8; ks++) {
        int k2 = ks * 2;
        uint32_t aH[4][4], aL[4][4], bH[4][2], bL[4][2];
        #pragma unroll
        for (int i = 0; i < 4; i++) {
            uint32_t ad = aBase[i] + (((k2 + a_cb) ^ aM7[i]) << 4);
            ldm_x4(aH[i], ad);
            ldm_x4(aL[i], ad + 32768);
        }
        #pragma unroll
        for (int j = 0; j < 4; j++) {
            uint32_t bd = bBase[j] + PJ_W2H + (((k2 + b_cb) ^ bM7[j]) << 4);
            ldm_x2(bH[j], bd);
            ldm_x2(bL[j], bd + 32768);
        }
        #pragma unroll
        for (int i = 0; i < 4; i++)
            #pragma unroll
            for (int j = 0; j < 4; j++) {
                mma_bf16(acc[i][j], aH[i], bH[j]);
                mma_bf16(acc[i][j], aH[i], bL[j]);
                mma_bf16(acc[i][j], aL[i], bH[j]);
            }
    }

    float* out = g_h2[net];
    #pragma unroll
    for (int j = 0; j < 4; j++) {
        int col0 = wn * 32 + j * 8 + t * 2;
        float bb0 = smf[PJ_BIAS/4 + 128 + col0], bb1 = smf[PJ_BIAS/4 + 128 + col0 + 1];
        float s0 = 0.f, q0 = 0.f, s1 = 0.f, q1 = 0.f;
        #pragma unroll
        for (int i = 0; i < 4; i++) {
            float v0 = acc[i][j][0] + bb0;
            float v1 = acc[i][j][1] + bb1;
            float v2 = acc[i][j][2] + bb0;
            float v3 = acc[i][j][3] + bb1;
            int rl = wm * 64 + i * 16 + g, rh = rl + 8;
            *(float2*)&out[(size_t)(r0 + rl) * FD + col0] = make_float2(v0, v1);
            *(float2*)&out[(size_t)(r0 + rh) * FD + col0] = make_float2(v2, v3);
            s0 += v0 + v2; q0 += v0*v0 + v2*v2;
            s1 += v1 + v3; q1 += v1*v1 + v3*v3;
        }
        atomicAdd(&smf[PJ_CS/4 + col0], s0);
        atomicAdd(&smf[PJ_CQ/4 + col0], q0);
        atomicAdd(&smf[PJ_CS/4 + col0 + 1], s1);
        atomicAdd(&smf[PJ_CQ/4 + col0 + 1], q1);
    }
    __syncthreads();
    if (tid < 128) {
        atomicAdd(&g_bn_sum[net][tid], smf[PJ_CS/4 + tid]);
        atomicAdd(&g_bn_sq[net][tid],  smf[PJ_CQ/4 + tid]);
    }
}

// ---------------- fused BNfinal + BN apply + L2 normalize + fp16 convert ------------------
__global__ void k_normsplit(const float* __restrict__ tg, const float* __restrict__ tbe,
                            const float* __restrict__ sg, const float* __restrict__ sbe) {
    int net = blockIdx.z;
    const float* h = g_h2[net];
    const float* gam = net ? sg : tg;
    const float* bet = net ? sbe : tbe;
    __half* dst = net ? g_Ah : g_Bh;   // student -> A, teacher -> B
    int w = threadIdx.x >> 5, l = threadIdx.x & 31;
    int r = blockIdx.x * 8 + w;

    float4 su = *(const float4*)&g_bn_sum[net][l*4];
    float4 sq = *(const float4*)&g_bn_sq[net][l*4];
    float4 gm = *(const float4*)&gam[l*4];
    float4 bt = *(const float4*)&bet[l*4];
    float sc[4], sh[4];
    {
        float mu, var;
        mu = su.x*(1.f/8192.f); var = sq.x*(1.f/8192.f) - mu*mu;
        sc[0] = rsqrtf(var + BN_EPS) * gm.x; sh[0] = bt.x - mu * sc[0];
        mu = su.y*(1.f/8192.f); var = sq.y*(1.f/8192.f) - mu*mu;
        sc[1] = rsqrtf(var + BN_EPS) * gm.y; sh[1] = bt.y - mu * sc[1];
        mu = su.z*(1.f/8192.f); var = sq.z*(1.f/8192.f) - mu*mu;
        sc[2] = rsqrtf(var + BN_EPS) * gm.z; sh[2] = bt.z - mu * sc[2];
        mu = su.w*(1.f/8192.f); var = sq.w*(1.f/8192.f) - mu*mu;
        sc[3] = rsqrtf(var + BN_EPS) * gm.w; sh[3] = bt.w - mu * sc[3];
    }
    float4 v = *(const float4*)&h[(size_t)r*FD + l*4];
    float y[4];
    y[0] = fmaf(v.x, sc[0], sh[0]); y[1] = fmaf(v.y, sc[1], sh[1]);
    y[2] = fmaf(v.z, sc[2], sh[2]); y[3] = fmaf(v.w, sc[3], sh[3]);
    float ss = y[0]*y[0] + y[1]*y[1] + y[2]*y[2] + y[3]*y[3];
    #pragma unroll
    for (int o = 16; o > 0; o >>= 1) ss += __shfl_xor_sync(0xffffffffu, ss, o);
    float inv = rsqrtf(ss);
    __half2 p0 = __floats2half2_rn(y[0]*inv, y[1]*inv);
    __half2 p1 = __floats2half2_rn(y[2]*inv, y[3]*inv);
    uint2 pk = make_uint2(*(uint32_t*)&p0, *(uint32_t*)&p1);
    *(uint2*)&dst[(size_t)r*FD + l*4] = pk;
}

// ---------------- fp16 single-pass HMMA GEMM -> int16 sims --------------------------------
// smem: A fp16 [128 x 128] at 0 (32KB), B at 32768 (32KB). row = 256B = 16 chunks.
// swizzle: swz(ch,row) = (ch & 8) | ((ch ^ row) & 7)
#define SM_GEMM 65536

__global__ __launch_bounds__(256, 2) void k_gemm() {
    if ((int)(blockIdx.y * 128) >= g_cnt) return;
    extern __shared__ char smc[];
    uint32_t sb = smem_to_u32(smc);
    int tid = threadIdx.x, lane = tid & 31, wid = tid >> 5;
    int wm = wid >> 2, wn = wid & 3;
    const int* mrow = &g_matched[blockIdx.y * 128];

    // cooperative cp.async fill: 2048 A chunks + 2048 B chunks (16B each)
    #pragma unroll
    for (int it = 0; it < 8; it++) {
        int idx = tid + it * 256;
        int row = idx >> 4, ch = idx & 15;
        uint32_t swz = (uint32_t)((ch & 8) | ((ch ^ row) & 7));
        uint32_t off = (uint32_t)row * 256 + (swz << 4);
        int ar = __ldg(&mrow[row]);
        cp16(sb + off,         (const char*)(g_Ah + (size_t)ar * FD) + ch * 16);
        cp16(sb + 32768 + off, (const char*)(g_Bh + (size_t)(blockIdx.x * 128 + row) * FD) + ch * 16);
    }
    cp_commit_wait();
    __syncthreads();

    int a_sub   = lane >> 3;
    int a_rowin = (lane & 7) + ((a_sub & 1) << 3);
    int a_cb    = a_sub >> 1;
    int b_rowin = lane & 7;
    int b_cb    = (lane >> 3) & 1;

    uint32_t aBase[4], bBase[4];
    int aM7[4], bM7[4];
    #pragma unroll
    for (int i = 0; i < 4; i++) {
        int row = wm * 64 + i * 16 + a_rowin;
        aBase[i] = sb + row * 256;
        aM7[i] = row & 7;
        int rn = wn * 32 + i * 8 + b_rowin;
        bBase[i] = sb + 32768 + rn * 256;
        bM7[i] = rn & 7;
    }

    float acc[4][4][4];
    #pragma unroll
    for (int i = 0; i < 4; i++)
        #pragma unroll
        for (int j = 0; j < 4; j++)
            #pragma unroll
            for (int q = 0; q < 4; q++) acc[i][j][q] = 0.f;

    #pragma unroll
    for (int ks = 0; ks < 8; ks++) {
        int k2 = ks * 2;
        uint32_t aF[4][4], bF[4][2];
        #pragma unroll
        for (int i = 0; i < 4; i++) {
            int c = k2 + a_cb;
            uint32_t swz = (uint32_t)((c & 8) | ((c ^ aM7[i]) & 7));
            ldm_x4(aF[i], aBase[i] + (swz << 4));
        }
        #pragma unroll
        for (int j = 0; j < 4; j++) {
            int c = k2 + b_cb;
            uint32_t swz = (uint32_t)((c & 8) | ((c ^ bM7[j]) & 7));
            ldm_x2(bF[j], bBase[j] + (swz << 4));
        }
        #pragma unroll
        for (int i = 0; i < 4; i++)
            #pragma unroll
            for (int j = 0; j < 4; j++)
                mma_f16(acc[i][j], aF[i], bF[j]);
    }

    // epilogue: quantize to int16, pack pairs, store
    int g = lane >> 2, t = lane & 3;
    size_t rowbase = (size_t)blockIdx.y * 128 + wm * 64 + g;
    int colbase = blockIdx.x * 128 + wn * 32 + t * 2;
    #pragma unroll
    for (int i = 0; i < 4; i++) {
        #pragma unroll
        for (int j = 0; j < 4; j++) {
            size_t r0 = (rowbase + i*16) * NT + colbase + j*8;
            int q0 = __float2int_rn(acc[i][j][0] * QSCALE);
            int q1 = __float2int_rn(acc[i][j][1] * QSCALE);
            int q2 = __float2int_rn(acc[i][j][2] * QSCALE);
            int q3 = __float2int_rn(acc[i][j][3] * QSCALE);
            *(uint32_t*)&g_simsq[r0]                 = (q0 & 0xFFFF) | (q1 << 16);
            *(uint32_t*)&g_simsq[r0 + (size_t)8*NT]  = (q2 & 0xFFFF) | (q3 << 16);
        }
    }
}

// ---------------- exact top-k + logsumexp per matched row (int16 domain) ------------------
#define SM_SEL ((4096 + 4096 + 512 + 16 + 16)*4)

__global__ __launch_bounds__(512) void k_select() {
    int bid = blockIdx.x;
    if (bid >= g_cnt) return;
    extern __shared__ int sms[];
    int* qrow = sms;
    int* hist = sms + 4096;
    int* red  = sms + 8192;
    int* h16  = sms + 8704;
    int* misc = sms + 8720;
    int tid = threadIdx.x;

    for (int i = tid; i < 4096; i += 512) hist[i] = 0;
    if (tid < 16) h16[tid] = 0;
    __syncthreads();

    const uint4* g4 = (const uint4*)(g_simsq + (size_t)bid * NT);
    int qmax = -131072;
    #pragma unroll
    for (int u = 0; u < 2; u++) {
        uint4 v = g4[tid + u*512];
        ((uint4*)qrow)[tid + u*512] = v;
        uint32_t ws[4] = {v.x, v.y, v.z, v.w};
        #pragma unroll
        for (int p = 0; p < 4; p++) {
            int q0 = (int)(short)(ws[p] & 0xFFFF);
            int q1 = (int)(short)(ws[p] >> 16);
            qmax = max(qmax, max(q0, q1));
            atomicAdd(&hist[(q0 + 32768) >> 4], 1);
            atomicAdd(&hist[(q1 + 32768) >> 4], 1);
        }
    }
    red[tid] = qmax;
    __syncthreads();
    for (int s = 256; s > 0; s >>= 1) {
        if (tid < s) red[tid] = max(red[tid], red[tid + s]);
        __syncthreads();
    }
    qmax = red[0];
    __syncthreads();

    int cs = 0;
    #pragma unroll
    for (int i = 0; i < 8; i++) cs += hist[tid*8 + i];
    red[tid] = cs;
    __syncthreads();
    for (int off = 1; off < 512; off <<= 1) {
        int v = red[tid] + ((tid + off < 512) ? red[tid + off] : 0);
        __syncthreads();
        red[tid] = v;
        __syncthreads();
    }
    int incl = red[tid];
    int inclNext = (tid < 511) ? red[tid + 1] : 0;
    if (incl >= KSEL && inclNext < KSEL) {
        int cum = inclNext;
        for (int b = tid*8 + 7; b >= tid*8; b--) {
            cum += hist[b];
            if (cum >= KSEL) { misc[0] = b; misc[1] = KSEL - (cum - hist[b]); break; }
        }
    }
    __syncthreads();
    int B = misc[0], j = misc[1];

    float z = 0.f;
    #pragma unroll
    for (int i = 0; i < 8; i++) {
        int w = qrow[tid + i*512];
        int q0 = (int)(short)(w & 0xFFFF);
        int q1 = (int)(short)(w >> 16);
        int b0 = (q0 + 32768) >> 4;
        int b1 = (q1 + 32768) >> 4;
        if (b0 > B) z += fexp((float)(q0 - qmax) * INV2048);
        else if (b0 == B) atomicAdd(&h16[(q0 + 32768) & 15], 1);
        if (b1 > B) z += fexp((float)(q1 - qmax) * INV2048);
        else if (b1 == B) atomicAdd(&h16[(q1 + 32768) & 15], 1);
    }
    __syncthreads();
    float* zred = (float*)red;
    zred[tid] = z;
    __syncthreads();
    for (int s = 256; s > 0; s >>= 1) {
        if (tid < s) zred[tid] += zred[tid + s];
        __syncthreads();
    }

    if (tid == 0) {
        float Z = zred[0];
        int need = j;
        for (int s = 15; s >= 0 && need > 0; s--) {
            int c = h16[s];
            if (c == 0) continue;
            int take = min(c, need);
            int q = B*16 + s - 32768;
            Z += (float)take * fexp((float)(q - qmax) * INV2048);
            need -= take;
        }
        int srow = g_matched[bid];
        int col = g_tidx[srow];
        int qpos = (int)((short*)qrow)[col];
        Z += fexp((float)(qpos - qmax) * INV2048);
        float pp = logf(Z) + (float)(qmax - qpos) * INV2048;
        atomicAdd(&g_accum, pp);
    }
}

// ---------------- finalize + keymap restore -----------------------------------------------
__global__ void k_fin(const int* __restrict__ tc, float* out) {
    int i = blockIdx.x * 256 + threadIdx.x;
    int4 c = ((const int4*)tc)[i];
    int key = ((c.x * 64 + c.y) * 128 + c.z) * 128 + c.w;
    g_keymap[key] = 0;
    if (i == 0) {
        int cnt = g_cnt;
        float d = (cnt > 0) ? (float)cnt : 1.0f;
        out[0] = g_accum / d;
    }
}

// ---------------- launch ------------------------------------------------------------------
extern "C" void kernel_launch(void* const* d_in, const int* in_sizes, int n_in,
                              void* d_out, int out_size) {
    const float* tf = (const float*)d_in[0];
    const float* sf = (const float*)d_in[1];
    const float* t_w1 = (const float*)d_in[2];
    const float* t_b1 = (const float*)d_in[3];
    const float* t_w2 = (const float*)d_in[4];
    const float* t_b2 = (const float*)d_in[5];
    const float* t_g  = (const float*)d_in[6];
    const float* t_be = (const float*)d_in[7];
    const float* s_w1 = (const float*)d_in[8];
    const float* s_b1 = (const float*)d_in[9];
    const float* s_w2 = (const float*)d_in[10];
    const float* s_b2 = (const float*)d_in[11];
    const float* s_g  = (const float*)d_in[12];
    const float* s_be = (const float*)d_in[13];
    const int* tco = (const int*)d_in[14];
    const int* sco = (const int*)d_in[15];

    cudaFuncSetAttribute(k_projmma, cudaFuncAttributeMaxDynamicSharedMemorySize, SM_PROJ);
    cudaFuncSetAttribute(k_gemm,    cudaFuncAttributeMaxDynamicSharedMemorySize, SM_GEMM);
    cudaFuncSetAttribute(k_select,  cudaFuncAttributeMaxDynamicSharedMemorySize, SM_SEL);

    k_prep<<<32, 256>>>(tco, t_w1, t_w2, s_w1, s_w2);           // 0
    k_projmma<<<dim3(64,1,2), 256, SM_PROJ>>>(tf, sf,           // 1 (+ match)
        t_b1, t_b2, s_b1, s_b2, sco);
    k_normsplit<<<dim3(1024,1,2), 256>>>(t_g, t_be, s_g, s_be); // 2
    k_gemm<<<dim3(64, 64), 256, SM_GEMM>>>();                   // 3  <- ncu captures this
    k_select<<<8192, 512, SM_SEL>>>();                          // 4
    k_fin<<<32, 256>>>(tco, (float*)d_out);                     // 5
}